// round 2
// baseline (speedup 1.0000x reference)
#include <cuda_runtime.h>

#define B_  8
#define N_  2048
#define M_  2048
#define DP_ 128
#define DM_ 256
#define K_  16
#define BN_  (B_*N_)        // 16384
#define BNK_ (B_*N_*K_)     // 262144

// ---------------- scratch (device globals: allocation-free rule) -------------
__device__ float g_q   [BN_*DM_];
__device__ float g_xs  [BN_*DM_];
__device__ float g_kall[BN_*DM_];
__device__ float g_vall[BN_*DM_];
__device__ float g_g   [(size_t)BNK_*DM_];   // g, later reused for pre-softmax a
__device__ float g_h   [(size_t)BNK_*DM_];
__device__ float g_vp  [(size_t)BNK_*DM_];   // vg + pos
__device__ float g_res [BN_*DM_];
__device__ float g_outtmp[BN_*DP_];
__device__ int   g_knn [BNK_];

// ---------------- KNN: exact expanded-form d2, stable top-16 -----------------
__global__ void __launch_bounds__(128) knn_k(const float* __restrict__ xyz,
                                             const float* __restrict__ xyzs)
{
    __shared__ float sy0[M_], sy1[M_], sy2[M_], syn[M_];
    int b = blockIdx.x;
    int n = blockIdx.y * 128 + threadIdx.x;
    const float* ys = xyzs + (size_t)b * M_ * 3;
    for (int m = threadIdx.x; m < M_; m += 128) {
        float y0 = ys[m*3+0], y1 = ys[m*3+1], y2 = ys[m*3+2];
        sy0[m] = y0; sy1[m] = y1; sy2[m] = y2;
        syn[m] = __fadd_rn(__fadd_rn(__fmul_rn(y0,y0), __fmul_rn(y1,y1)), __fmul_rn(y2,y2));
    }
    __syncthreads();

    const float* x = xyz + ((size_t)b * N_ + n) * 3;
    float x0 = x[0], x1 = x[1], x2 = x[2];
    float xn = __fadd_rn(__fadd_rn(__fmul_rn(x0,x0), __fmul_rn(x1,x1)), __fmul_rn(x2,x2));

    float bd[K_]; int bi[K_];
    #pragma unroll
    for (int k = 0; k < K_; k++) { bd[k] = 3.4e38f; bi[k] = 0; }

    for (int m = 0; m < M_; m++) {
        float dot = __fadd_rn(__fadd_rn(__fmul_rn(x0, sy0[m]), __fmul_rn(x1, sy1[m])),
                              __fmul_rn(x2, sy2[m]));
        float d2 = __fsub_rn(__fadd_rn(xn, syn[m]), __fmul_rn(2.0f, dot));
        if (d2 < bd[K_-1]) {
            int p = K_ - 1;
            while (p > 0 && bd[p-1] > d2) { bd[p] = bd[p-1]; bi[p] = bi[p-1]; p--; }
            bd[p] = d2; bi[p] = m;   // stable: equal keeps earlier (lower) index first
        }
    }
    size_t base = ((size_t)b * N_ + n) * K_;
    #pragma unroll
    for (int k = 0; k < K_; k++) g_knn[base + k] = bi[k];
}

// ---------------- generic fp32 SGEMM: C = A[rows,kd] * W[kd,wn] + bias -------
template<bool RELU, bool ADDSRC>
__global__ void __launch_bounds__(256, 2)
sgemm_k(const float* __restrict__ A, int kd,
        const float* __restrict__ W, int wn,
        const float* __restrict__ bias,
        const float* __restrict__ Add,
        float* __restrict__ C, int rows)
{
    __shared__ float As[16][128];
    __shared__ float Bs[16][128];
    int row0 = blockIdx.x * 128;
    int col0 = blockIdx.y * 128;
    int tid = threadIdx.x;
    int tm = tid >> 4, tn = tid & 15;

    float acc[8][8];
    #pragma unroll
    for (int i = 0; i < 8; i++)
        #pragma unroll
        for (int j = 0; j < 8; j++) acc[i][j] = 0.0f;

    for (int k0 = 0; k0 < kd; k0 += 16) {
        #pragma unroll
        for (int i = 0; i < 2; i++) {
            int f = tid + i * 256;        // 0..511
            int r = f >> 2;               // 0..127
            int kc = (f & 3) << 2;        // 0,4,8,12
            float4 v = *reinterpret_cast<const float4*>(A + (size_t)(row0 + r) * kd + k0 + kc);
            As[kc+0][r] = v.x; As[kc+1][r] = v.y; As[kc+2][r] = v.z; As[kc+3][r] = v.w;
        }
        #pragma unroll
        for (int i = 0; i < 2; i++) {
            int f = tid + i * 256;
            int kr = f >> 5;              // 0..15
            int jc = (f & 31) << 2;       // 0..124
            *reinterpret_cast<float4*>(&Bs[kr][jc]) =
                *reinterpret_cast<const float4*>(W + (size_t)(k0 + kr) * wn + col0 + jc);
        }
        __syncthreads();
        #pragma unroll
        for (int kk = 0; kk < 16; kk++) {
            float4 a0 = *reinterpret_cast<const float4*>(&As[kk][tm*8]);
            float4 a1 = *reinterpret_cast<const float4*>(&As[kk][tm*8+4]);
            float4 b0 = *reinterpret_cast<const float4*>(&Bs[kk][tn*8]);
            float4 b1 = *reinterpret_cast<const float4*>(&Bs[kk][tn*8+4]);
            float ar[8] = {a0.x,a0.y,a0.z,a0.w,a1.x,a1.y,a1.z,a1.w};
            float br[8] = {b0.x,b0.y,b0.z,b0.w,b1.x,b1.y,b1.z,b1.w};
            #pragma unroll
            for (int i = 0; i < 8; i++)
                #pragma unroll
                for (int j = 0; j < 8; j++)
                    acc[i][j] = fmaf(ar[i], br[j], acc[i][j]);
        }
        __syncthreads();
    }

    float bj[8];
    #pragma unroll
    for (int j = 0; j < 8; j++) bj[j] = bias ? bias[col0 + tn*8 + j] : 0.0f;

    #pragma unroll
    for (int i = 0; i < 8; i++) {
        int r = row0 + tm*8 + i;
        float* crow = C + (size_t)r * wn + col0 + tn*8;
        const float* arow = ADDSRC ? (Add + (size_t)r * wn + col0 + tn*8) : nullptr;
        float v[8];
        #pragma unroll
        for (int j = 0; j < 8; j++) {
            float t = acc[i][j] + bj[j];
            if (RELU)   t = fmaxf(t, 0.0f);
            if (ADDSRC) t = arow[j] + t;
            v[j] = t;
        }
        *reinterpret_cast<float4*>(crow)     = make_float4(v[0],v[1],v[2],v[3]);
        *reinterpret_cast<float4*>(crow + 4) = make_float4(v[4],v[5],v[6],v[7]);
    }
}

// ------- fused pos GEMM: A = relu(delta@fd1 + b) generated on the fly --------
// epilogue: pos = acc + fd2_b ; g = q - kg + pos ; vp = vg + pos
__global__ void __launch_bounds__(256, 2)
posg_k(const float* __restrict__ xyz, const float* __restrict__ xyzs,
       const float* __restrict__ fd1w, const float* __restrict__ fd1b,
       const float* __restrict__ fd2w, const float* __restrict__ fd2b)
{
    __shared__ float As[16][128];
    __shared__ float Bs[16][128];
    __shared__ float sDel[3][128];
    __shared__ int   sQ[128], sS[128];
    __shared__ float sF0[DM_], sF1[DM_], sF2[DM_], sFb[DM_];

    int row0 = blockIdx.x * 128;
    int col0 = blockIdx.y * 128;
    int tid  = threadIdx.x;
    int tm = tid >> 4, tn = tid & 15;

    if (tid < 256) { sF0[tid] = fd1w[tid]; sF1[tid] = fd1w[256+tid]; sF2[tid] = fd1w[512+tid]; sFb[tid] = fd1b[tid]; }
    if (tid < 128) {
        int r = row0 + tid;
        int b = r >> 15;                 // / (N_*K_)
        int rem = r & 32767;
        int n = rem >> 4;
        int i = g_knn[r];
        sQ[tid] = b * N_ + n;
        sS[tid] = b * M_ + i;
        const float* x = xyz  + ((size_t)b * N_ + n) * 3;
        const float* y = xyzs + ((size_t)b * M_ + i) * 3;
        sDel[0][tid] = x[0]-y[0]; sDel[1][tid] = x[1]-y[1]; sDel[2][tid] = x[2]-y[2];
    }
    __syncthreads();

    float acc[8][8];
    #pragma unroll
    for (int i = 0; i < 8; i++)
        #pragma unroll
        for (int j = 0; j < 8; j++) acc[i][j] = 0.0f;

    for (int k0 = 0; k0 < DM_; k0 += 16) {
        #pragma unroll
        for (int e = 0; e < 8; e++) {
            int f = tid + e * 256;        // 0..2047
            int r = f & 127;
            int k = f >> 7;               // 0..15
            int t = k0 + k;
            float h = fmaf(sDel[0][r], sF0[t],
                      fmaf(sDel[1][r], sF1[t],
                      fmaf(sDel[2][r], sF2[t], sFb[t])));
            As[k][r] = fmaxf(h, 0.0f);
        }
        #pragma unroll
        for (int i = 0; i < 2; i++) {
            int f = tid + i * 256;
            int kr = f >> 5;
            int jc = (f & 31) << 2;
            *reinterpret_cast<float4*>(&Bs[kr][jc]) =
                *reinterpret_cast<const float4*>(fd2w + (size_t)(k0 + kr) * DM_ + col0 + jc);
        }
        __syncthreads();
        #pragma unroll
        for (int kk = 0; kk < 16; kk++) {
            float4 a0 = *reinterpret_cast<const float4*>(&As[kk][tm*8]);
            float4 a1 = *reinterpret_cast<const float4*>(&As[kk][tm*8+4]);
            float4 b0 = *reinterpret_cast<const float4*>(&Bs[kk][tn*8]);
            float4 b1 = *reinterpret_cast<const float4*>(&Bs[kk][tn*8+4]);
            float ar[8] = {a0.x,a0.y,a0.z,a0.w,a1.x,a1.y,a1.z,a1.w};
            float br[8] = {b0.x,b0.y,b0.z,b0.w,b1.x,b1.y,b1.z,b1.w};
            #pragma unroll
            for (int i = 0; i < 8; i++)
                #pragma unroll
                for (int j = 0; j < 8; j++)
                    acc[i][j] = fmaf(ar[i], br[j], acc[i][j]);
        }
        __syncthreads();
    }

    float bj[8];
    #pragma unroll
    for (int j = 0; j < 8; j++) bj[j] = fd2b[col0 + tn*8 + j];

    #pragma unroll
    for (int i = 0; i < 8; i++) {
        int rr = tm*8 + i;
        int r = row0 + rr;
        const float* qrow = g_q    + (size_t)sQ[rr] * DM_ + col0 + tn*8;
        const float* krow = g_kall + (size_t)sS[rr] * DM_ + col0 + tn*8;
        const float* vrow = g_vall + (size_t)sS[rr] * DM_ + col0 + tn*8;
        float* grow  = g_g  + (size_t)r * DM_ + col0 + tn*8;
        float* vprow = g_vp + (size_t)r * DM_ + col0 + tn*8;
        float gv[8], vv[8];
        #pragma unroll
        for (int j = 0; j < 8; j++) {
            float pos = acc[i][j] + bj[j];
            gv[j] = qrow[j] - krow[j] + pos;
            vv[j] = vrow[j] + pos;
        }
        *reinterpret_cast<float4*>(grow)      = make_float4(gv[0],gv[1],gv[2],gv[3]);
        *reinterpret_cast<float4*>(grow + 4)  = make_float4(gv[4],gv[5],gv[6],gv[7]);
        *reinterpret_cast<float4*>(vprow)     = make_float4(vv[0],vv[1],vv[2],vv[3]);
        *reinterpret_cast<float4*>(vprow + 4) = make_float4(vv[4],vv[5],vv[6],vv[7]);
    }
}

// -------- softmax over K (scale 1/16) + weighted reduce over (vg+pos) --------
__global__ void __launch_bounds__(256) smred_k(float* __restrict__ attn_out, int write_attn)
{
    int bn = blockIdx.x;
    int j  = threadIdx.x;
    const float* ap  = g_g  + (size_t)bn * K_ * DM_ + j;   // 'a' lives in g_g
    const float* vpp = g_vp + (size_t)bn * K_ * DM_ + j;

    float av[K_];
    float mx = -3.4e38f;
    #pragma unroll
    for (int k = 0; k < K_; k++) { av[k] = ap[k*DM_] * 0.0625f; mx = fmaxf(mx, av[k]); }
    float s = 0.0f;
    #pragma unroll
    for (int k = 0; k < K_; k++) { av[k] = expf(av[k] - mx); s += av[k]; }
    float inv = 1.0f / s;
    float res = 0.0f;
    #pragma unroll
    for (int k = 0; k < K_; k++) {
        float a = av[k] * inv;
        if (write_attn) attn_out[((size_t)bn * K_ + k) * DM_ + j] = a;
        res = fmaf(a, vpp[k*DM_], res);
    }
    g_res[(size_t)bn * DM_ + j] = res;
}

// --------------------------------- launch ------------------------------------
extern "C" void kernel_launch(void* const* d_in, const int* in_sizes, int n_in,
                              void* d_out, int out_size)
{
    const float* xyz   = (const float*)d_in[0];
    const float* feat  = (const float*)d_in[1];
    const float* xyzs  = (const float*)d_in[2];
    const float* feats = (const float*)d_in[3];
    const float* fc1w  = (const float*)d_in[4];
    const float* fc1b  = (const float*)d_in[5];
    const float* fc1sw = (const float*)d_in[6];
    const float* fc1sb = (const float*)d_in[7];
    const float* fc2w  = (const float*)d_in[8];
    const float* fc2b  = (const float*)d_in[9];
    const float* fd1w  = (const float*)d_in[10];
    const float* fd1b  = (const float*)d_in[11];
    const float* fd2w  = (const float*)d_in[12];
    const float* fd2b  = (const float*)d_in[13];
    const float* fg1w  = (const float*)d_in[14];
    const float* fg1b  = (const float*)d_in[15];
    const float* fg2w  = (const float*)d_in[16];
    const float* fg2b  = (const float*)d_in[17];
    const float* wk    = (const float*)d_in[18];
    const float* wv    = (const float*)d_in[19];

    static bool init = false;
    static float *p_q, *p_xs, *p_k, *p_v, *p_g, *p_h, *p_res, *p_outtmp;
    if (!init) {
        cudaGetSymbolAddress((void**)&p_q,  g_q);
        cudaGetSymbolAddress((void**)&p_xs, g_xs);
        cudaGetSymbolAddress((void**)&p_k,  g_kall);
        cudaGetSymbolAddress((void**)&p_v,  g_vall);
        cudaGetSymbolAddress((void**)&p_g,  g_g);
        cudaGetSymbolAddress((void**)&p_h,  g_h);
        cudaGetSymbolAddress((void**)&p_res, g_res);
        cudaGetSymbolAddress((void**)&p_outtmp, g_outtmp);
        init = true;
    }

    const long long OUTE  = (long long)BN_ * DP_;     //  2,097,152
    const long long ATTNE = (long long)BNK_ * DM_;    // 67,108,864
    float* out = (float*)d_out;
    float* out_main; float* out_attn; int write_attn;
    if ((long long)out_size >= OUTE + ATTNE) { out_main = out; out_attn = out + OUTE; write_attn = 1; }
    else if ((long long)out_size == ATTNE)   { out_main = p_outtmp; out_attn = out; write_attn = 1; }
    else                                      { out_main = out; out_attn = nullptr; write_attn = 0; }

    // 1. KNN
    knn_k<<<dim3(B_, N_/128), 128>>>(xyz, xyzs);
    // 2. q = features @ fc1 + b ; xs = features_surface @ fc1s + b
    sgemm_k<false,false><<<dim3(BN_/128, 2), 256>>>(feat,  DP_, fc1w,  DM_, fc1b,  nullptr, p_q,  BN_);
    sgemm_k<false,false><<<dim3(BN_/128, 2), 256>>>(feats, DP_, fc1sw, DM_, fc1sb, nullptr, p_xs, BN_);
    // 3. k_all = xs @ wk ; v_all = xs @ wv
    sgemm_k<false,false><<<dim3(BN_/128, 2), 256>>>(p_xs, DM_, wk, DM_, nullptr, nullptr, p_k, BN_);
    sgemm_k<false,false><<<dim3(BN_/128, 2), 256>>>(p_xs, DM_, wv, DM_, nullptr, nullptr, p_v, BN_);
    // 4. fused pos GEMM -> g, vp
    posg_k<<<dim3(BNK_/128, 2), 256>>>(xyz, xyzs, fd1w, fd1b, fd2w, fd2b);
    // 5. h = relu(g @ fg1 + b)
    sgemm_k<true,false><<<dim3(BNK_/128, 2), 256>>>(p_g, DM_, fg1w, DM_, fg1b, nullptr, p_h, BNK_);
    // 6. a = h @ fg2 + b  (into g_g)
    sgemm_k<false,false><<<dim3(BNK_/128, 2), 256>>>(p_h, DM_, fg2w, DM_, fg2b, nullptr, p_g, BNK_);
    // 7. softmax over K + reduce with vp -> res (+ attn output)
    smred_k<<<BN_, 256>>>(out_attn, write_attn);
    // 8. out = features + res @ fc2 + b
    sgemm_k<false,true><<<dim3(BN_/128, 1), 256>>>(p_res, DM_, fc2w, DP_, fc2b, feat, out_main, BN_);
}

// round 3
// speedup vs baseline: 1.1982x; 1.1982x over previous
#include <cuda_runtime.h>
#include <cuda_bf16.h>
#include <mma.h>
using namespace nvcuda;

#define B_  8
#define N_  2048
#define M_  2048
#define DP_ 128
#define DM_ 256
#define K_  16
#define BN_  (B_*N_)        // 16384
#define BNK_ (B_*N_*K_)     // 262144

typedef __nv_bfloat16 bf16;
typedef __nv_bfloat162 bf162;

// ---------------- scratch (device globals: allocation-free rule) -------------
__device__ bf16  g_featb [BN_*DP_];
__device__ bf16  g_featsb[BN_*DP_];
__device__ bf16  g_qb [BN_*DM_];
__device__ bf16  g_xsb[BN_*DM_];
__device__ bf16  g_kb [BN_*DM_];
__device__ bf16  g_vb [BN_*DM_];
__device__ bf16  g_gb [(size_t)BNK_*DM_];   // g, later reused for pre-softmax a
__device__ bf16  g_hb [(size_t)BNK_*DM_];
__device__ bf16  g_vpb[(size_t)BNK_*DM_];   // vg + pos
__device__ bf16  g_resb[BN_*DM_];
__device__ float g_outtmp[BN_*DP_];
__device__ int   g_knn [BNK_];
__device__ float g_zerobias[DM_];           // zero-initialized

// bf16 weight copies
__device__ bf16 g_w_fc1 [DP_*DM_];
__device__ bf16 g_w_fc1s[DP_*DM_];
__device__ bf16 g_w_wk  [DM_*DM_];
__device__ bf16 g_w_wv  [DM_*DM_];
__device__ bf16 g_w_fd2 [DM_*DM_];
__device__ bf16 g_w_fg1 [DM_*DM_];
__device__ bf16 g_w_fg2 [DM_*DM_];
__device__ bf16 g_w_fc2 [DM_*DP_];

// ---------------- fp32 -> bf16 convert ---------------------------------------
__global__ void cvt_k(const float* __restrict__ src, bf16* __restrict__ dst, int n)
{
    int i = (blockIdx.x * 256 + threadIdx.x) * 2;
    if (i < n) {
        float2 v = *reinterpret_cast<const float2*>(src + i);
        *reinterpret_cast<bf162*>(dst + i) = __float22bfloat162_rn(v);
    }
}

// ---------------- KNN: exact expanded-form d2, stable top-16 -----------------
__global__ void __launch_bounds__(128) knn_k(const float* __restrict__ xyz,
                                             const float* __restrict__ xyzs)
{
    __shared__ float sy0[M_], sy1[M_], sy2[M_], syn[M_];
    int b = blockIdx.x;
    int n = blockIdx.y * 128 + threadIdx.x;
    const float* ys = xyzs + (size_t)b * M_ * 3;
    for (int m = threadIdx.x; m < M_; m += 128) {
        float y0 = ys[m*3+0], y1 = ys[m*3+1], y2 = ys[m*3+2];
        sy0[m] = y0; sy1[m] = y1; sy2[m] = y2;
        syn[m] = __fadd_rn(__fadd_rn(__fmul_rn(y0,y0), __fmul_rn(y1,y1)), __fmul_rn(y2,y2));
    }
    __syncthreads();

    const float* x = xyz + ((size_t)b * N_ + n) * 3;
    float x0 = x[0], x1 = x[1], x2 = x[2];
    float xn = __fadd_rn(__fadd_rn(__fmul_rn(x0,x0), __fmul_rn(x1,x1)), __fmul_rn(x2,x2));

    float bd[K_]; int bi[K_];
    #pragma unroll
    for (int k = 0; k < K_; k++) { bd[k] = 3.4e38f; bi[k] = 0; }

    for (int m = 0; m < M_; m++) {
        float dot = __fadd_rn(__fadd_rn(__fmul_rn(x0, sy0[m]), __fmul_rn(x1, sy1[m])),
                              __fmul_rn(x2, sy2[m]));
        float d2 = __fsub_rn(__fadd_rn(xn, syn[m]), __fmul_rn(2.0f, dot));
        if (d2 < bd[K_-1]) {
            int p = K_ - 1;
            while (p > 0 && bd[p-1] > d2) { bd[p] = bd[p-1]; bi[p] = bi[p-1]; p--; }
            bd[p] = d2; bi[p] = m;   // stable: equal keeps earlier (lower) index
        }
    }
    size_t base = ((size_t)b * N_ + n) * K_;
    #pragma unroll
    for (int k = 0; k < K_; k++) g_knn[base + k] = bi[k];
}

// ---------------- bf16 wmma GEMM: C = act(A[rows,kd] @ W[kd,wn] + bias) ------
// block tile 128x128, 8 warps (warp tile 32x64), BK=32
template<bool RELU, bool ADDSRC, bool OUTBF>
__global__ void __launch_bounds__(256, 2)
hgemm_k(const bf16* __restrict__ A, int kd,
        const bf16* __restrict__ W, int wn,
        const float* __restrict__ bias,
        const float* __restrict__ Add,   // fp32 add source (stride wn)
        void* __restrict__ Cout, int rows)
{
    __shared__ bf16 As[128][40];
    __shared__ bf16 Bs[32][136];
    __shared__ float Cs[8][16][20];

    int row0 = blockIdx.x * 128;
    int col0 = blockIdx.y * 128;
    int tid = threadIdx.x;
    int wid = tid >> 5, lane = tid & 31;
    int wr = (wid >> 1) * 32;
    int wc = (wid & 1) * 64;

    wmma::fragment<wmma::accumulator, 16,16,16, float> acc[2][4];
    #pragma unroll
    for (int i=0;i<2;i++)
        #pragma unroll
        for (int j=0;j<4;j++) wmma::fill_fragment(acc[i][j], 0.0f);

    for (int k0 = 0; k0 < kd; k0 += 32) {
        #pragma unroll
        for (int i=0;i<2;i++){
            int f = tid + i*256;
            int r = f >> 2, c = (f & 3) * 8;
            *reinterpret_cast<uint4*>(&As[r][c]) =
                *reinterpret_cast<const uint4*>(A + (size_t)(row0+r)*kd + k0 + c);
        }
        #pragma unroll
        for (int i=0;i<2;i++){
            int f = tid + i*256;
            int r = f >> 4, c = (f & 15) * 8;
            *reinterpret_cast<uint4*>(&Bs[r][c]) =
                *reinterpret_cast<const uint4*>(W + (size_t)(k0+r)*wn + col0 + c);
        }
        __syncthreads();
        #pragma unroll
        for (int kk = 0; kk < 32; kk += 16) {
            wmma::fragment<wmma::matrix_a, 16,16,16, bf16, wmma::row_major> af[2];
            wmma::fragment<wmma::matrix_b, 16,16,16, bf16, wmma::row_major> bfr[4];
            #pragma unroll
            for (int i=0;i<2;i++) wmma::load_matrix_sync(af[i], &As[wr+i*16][kk], 40);
            #pragma unroll
            for (int j=0;j<4;j++) wmma::load_matrix_sync(bfr[j], &Bs[kk][wc+j*16], 136);
            #pragma unroll
            for (int i=0;i<2;i++)
                #pragma unroll
                for (int j=0;j<4;j++)
                    wmma::mma_sync(acc[i][j], af[i], bfr[j], acc[i][j]);
        }
        __syncthreads();
    }

    #pragma unroll
    for (int i=0;i<2;i++)
        #pragma unroll
        for (int j=0;j<4;j++) {
            wmma::store_matrix_sync(&Cs[wid][0][0], acc[i][j], 20, wmma::mem_row_major);
            __syncwarp();
            int rbase = row0 + wr + i*16;
            int cbase = col0 + wc + j*16;
            #pragma unroll
            for (int e=0;e<4;e++){
                int p  = lane*4 + e;
                int rr = p >> 3;
                int cc = (p & 7) * 2;
                float v0 = Cs[wid][rr][cc]   + bias[cbase+cc];
                float v1 = Cs[wid][rr][cc+1] + bias[cbase+cc+1];
                if (RELU){ v0 = fmaxf(v0,0.f); v1 = fmaxf(v1,0.f); }
                size_t off = (size_t)(rbase+rr)*wn + cbase + cc;
                if (ADDSRC){ v0 += Add[off]; v1 += Add[off+1]; }
                if (OUTBF){
                    *reinterpret_cast<bf162*>(reinterpret_cast<bf16*>(Cout) + off) =
                        __float22bfloat162_rn(make_float2(v0,v1));
                } else {
                    *reinterpret_cast<float2*>(reinterpret_cast<float*>(Cout) + off) =
                        make_float2(v0,v1);
                }
            }
            __syncwarp();
        }
}

// ------- fused pos GEMM (bf16 MMA): A = relu(delta@fd1 + b) on the fly -------
// epilogue: pos = acc + fd2_b ; g = q - kg + pos ; vp = vg + pos  (both bf16)
__global__ void __launch_bounds__(256, 2)
posg_k(const float* __restrict__ xyz, const float* __restrict__ xyzs,
       const float* __restrict__ fd1w, const float* __restrict__ fd1b,
       const float* __restrict__ fd2b)
{
    __shared__ bf16 As[128][40];
    __shared__ bf16 Bs[32][136];
    __shared__ float Cs[8][16][20];
    __shared__ float sDel[3][128];
    __shared__ int   sQ[128], sS[128];
    __shared__ float sF0[DM_], sF1[DM_], sF2[DM_], sFb[DM_];

    int row0 = blockIdx.x * 128;
    int col0 = blockIdx.y * 128;
    int tid  = threadIdx.x;
    int wid = tid >> 5, lane = tid & 31;
    int wr = (wid >> 1) * 32;
    int wc = (wid & 1) * 64;

    sF0[tid] = fd1w[tid]; sF1[tid] = fd1w[256+tid]; sF2[tid] = fd1w[512+tid]; sFb[tid] = fd1b[tid];
    if (tid < 128) {
        int r = row0 + tid;
        int b = r >> 15;                 // / (N_*K_)
        int rem = r & 32767;
        int n = rem >> 4;
        int i = g_knn[r];
        sQ[tid] = b * N_ + n;
        sS[tid] = b * M_ + i;
        const float* x = xyz  + ((size_t)b * N_ + n) * 3;
        const float* y = xyzs + ((size_t)b * M_ + i) * 3;
        sDel[0][tid] = x[0]-y[0]; sDel[1][tid] = x[1]-y[1]; sDel[2][tid] = x[2]-y[2];
    }
    __syncthreads();

    wmma::fragment<wmma::accumulator, 16,16,16, float> acc[2][4];
    #pragma unroll
    for (int i=0;i<2;i++)
        #pragma unroll
        for (int j=0;j<4;j++) wmma::fill_fragment(acc[i][j], 0.0f);

    for (int k0 = 0; k0 < DM_; k0 += 32) {
        // generate A tile: As[r][k] = relu(delta[r].fd1[:,k0+k] + b)
        #pragma unroll
        for (int e = 0; e < 16; e++) {
            int f = tid + e * 256;        // 0..4095
            int r = f & 127;
            int k = f >> 7;               // 0..31
            int t = k0 + k;
            float h = fmaf(sDel[0][r], sF0[t],
                      fmaf(sDel[1][r], sF1[t],
                      fmaf(sDel[2][r], sF2[t], sFb[t])));
            As[r][k] = __float2bfloat16(fmaxf(h, 0.0f));
        }
        #pragma unroll
        for (int i=0;i<2;i++){
            int f = tid + i*256;
            int r = f >> 4, c = (f & 15) * 8;
            *reinterpret_cast<uint4*>(&Bs[r][c]) =
                *reinterpret_cast<const uint4*>(g_w_fd2 + (size_t)(k0+r)*DM_ + col0 + c);
        }
        __syncthreads();
        #pragma unroll
        for (int kk = 0; kk < 32; kk += 16) {
            wmma::fragment<wmma::matrix_a, 16,16,16, bf16, wmma::row_major> af[2];
            wmma::fragment<wmma::matrix_b, 16,16,16, bf16, wmma::row_major> bfr[4];
            #pragma unroll
            for (int i=0;i<2;i++) wmma::load_matrix_sync(af[i], &As[wr+i*16][kk], 40);
            #pragma unroll
            for (int j=0;j<4;j++) wmma::load_matrix_sync(bfr[j], &Bs[kk][wc+j*16], 136);
            #pragma unroll
            for (int i=0;i<2;i++)
                #pragma unroll
                for (int j=0;j<4;j++)
                    wmma::mma_sync(acc[i][j], af[i], bfr[j], acc[i][j]);
        }
        __syncthreads();
    }

    #pragma unroll
    for (int i=0;i<2;i++)
        #pragma unroll
        for (int j=0;j<4;j++) {
            wmma::store_matrix_sync(&Cs[wid][0][0], acc[i][j], 20, wmma::mem_row_major);
            __syncwarp();
            int rloc  = wr + i*16;
            int cbase = col0 + wc + j*16;
            #pragma unroll
            for (int e=0;e<4;e++){
                int p  = lane*4 + e;
                int rr = p >> 3;
                int cc = (p & 7) * 2;
                int rl = rloc + rr;
                int r  = row0 + rl;
                float pos0 = Cs[wid][rr][cc]   + fd2b[cbase+cc];
                float pos1 = Cs[wid][rr][cc+1] + fd2b[cbase+cc+1];
                size_t qoff = (size_t)sQ[rl] * DM_ + cbase + cc;
                size_t soff = (size_t)sS[rl] * DM_ + cbase + cc;
                float2 qv = __bfloat1622float2(*reinterpret_cast<const bf162*>(g_qb + qoff));
                float2 kv = __bfloat1622float2(*reinterpret_cast<const bf162*>(g_kb + soff));
                float2 vv = __bfloat1622float2(*reinterpret_cast<const bf162*>(g_vb + soff));
                size_t off = (size_t)r * DM_ + cbase + cc;
                *reinterpret_cast<bf162*>(g_gb + off) =
                    __float22bfloat162_rn(make_float2(qv.x - kv.x + pos0, qv.y - kv.y + pos1));
                *reinterpret_cast<bf162*>(g_vpb + off) =
                    __float22bfloat162_rn(make_float2(vv.x + pos0, vv.y + pos1));
            }
            __syncwarp();
        }
}

// -------- softmax over K (scale 1/16) + weighted reduce over (vg+pos) --------
__global__ void __launch_bounds__(256) smred_k(float* __restrict__ attn_out, int write_attn)
{
    int bn = blockIdx.x;
    int j  = threadIdx.x;
    const bf16* ap  = g_gb  + (size_t)bn * K_ * DM_ + j;   // 'a' lives in g_gb
    const bf16* vpp = g_vpb + (size_t)bn * K_ * DM_ + j;

    float av[K_];
    float mx = -3.4e38f;
    #pragma unroll
    for (int k = 0; k < K_; k++) {
        av[k] = __bfloat162float(ap[k*DM_]) * 0.0625f;
        mx = fmaxf(mx, av[k]);
    }
    float s = 0.0f;
    #pragma unroll
    for (int k = 0; k < K_; k++) { av[k] = expf(av[k] - mx); s += av[k]; }
    float inv = 1.0f / s;
    float res = 0.0f;
    #pragma unroll
    for (int k = 0; k < K_; k++) {
        float a = av[k] * inv;
        if (write_attn) attn_out[((size_t)bn * K_ + k) * DM_ + j] = a;
        res = fmaf(a, __bfloat162float(vpp[k*DM_]), res);
    }
    g_resb[(size_t)bn * DM_ + j] = __float2bfloat16(res);
}

// --------------------------------- launch ------------------------------------
extern "C" void kernel_launch(void* const* d_in, const int* in_sizes, int n_in,
                              void* d_out, int out_size)
{
    const float* xyz   = (const float*)d_in[0];
    const float* feat  = (const float*)d_in[1];
    const float* xyzs  = (const float*)d_in[2];
    const float* feats = (const float*)d_in[3];
    const float* fc1w  = (const float*)d_in[4];
    const float* fc1b  = (const float*)d_in[5];
    const float* fc1sw = (const float*)d_in[6];
    const float* fc1sb = (const float*)d_in[7];
    const float* fc2w  = (const float*)d_in[8];
    const float* fc2b  = (const float*)d_in[9];
    const float* fd1w  = (const float*)d_in[10];
    const float* fd1b  = (const float*)d_in[11];
    const float* fd2w  = (const float*)d_in[12];
    const float* fd2b  = (const float*)d_in[13];
    const float* fg1w  = (const float*)d_in[14];
    const float* fg1b  = (const float*)d_in[15];
    const float* fg2w  = (const float*)d_in[16];
    const float* fg2b  = (const float*)d_in[17];
    const float* wk    = (const float*)d_in[18];
    const float* wv    = (const float*)d_in[19];

    static bool init = false;
    static bf16 *p_featb, *p_featsb, *p_qb, *p_xsb, *p_kb, *p_vb, *p_gb, *p_hb, *p_resb;
    static bf16 *pw_fc1, *pw_fc1s, *pw_wk, *pw_wv, *pw_fd2, *pw_fg1, *pw_fg2, *pw_fc2;
    static float *p_outtmp, *p_zero;
    if (!init) {
        cudaGetSymbolAddress((void**)&p_featb,  g_featb);
        cudaGetSymbolAddress((void**)&p_featsb, g_featsb);
        cudaGetSymbolAddress((void**)&p_qb,  g_qb);
        cudaGetSymbolAddress((void**)&p_xsb, g_xsb);
        cudaGetSymbolAddress((void**)&p_kb,  g_kb);
        cudaGetSymbolAddress((void**)&p_vb,  g_vb);
        cudaGetSymbolAddress((void**)&p_gb,  g_gb);
        cudaGetSymbolAddress((void**)&p_hb,  g_hb);
        cudaGetSymbolAddress((void**)&p_resb, g_resb);
        cudaGetSymbolAddress((void**)&pw_fc1,  g_w_fc1);
        cudaGetSymbolAddress((void**)&pw_fc1s, g_w_fc1s);
        cudaGetSymbolAddress((void**)&pw_wk,   g_w_wk);
        cudaGetSymbolAddress((void**)&pw_wv,   g_w_wv);
        cudaGetSymbolAddress((void**)&pw_fd2,  g_w_fd2);
        cudaGetSymbolAddress((void**)&pw_fg1,  g_w_fg1);
        cudaGetSymbolAddress((void**)&pw_fg2,  g_w_fg2);
        cudaGetSymbolAddress((void**)&pw_fc2,  g_w_fc2);
        cudaGetSymbolAddress((void**)&p_outtmp, g_outtmp);
        cudaGetSymbolAddress((void**)&p_zero,   g_zerobias);
        init = true;
    }

    const long long OUTE  = (long long)BN_ * DP_;     //  2,097,152
    const long long ATTNE = (long long)BNK_ * DM_;    // 67,108,864
    float* out = (float*)d_out;
    float* out_main; float* out_attn; int write_attn;
    if ((long long)out_size >= OUTE + ATTNE) { out_main = out; out_attn = out + OUTE; write_attn = 1; }
    else if ((long long)out_size == ATTNE)   { out_main = p_outtmp; out_attn = out; write_attn = 1; }
    else                                      { out_main = out; out_attn = nullptr; write_attn = 0; }

    // 0. conversions to bf16
    auto CVT = [](const float* s, bf16* d, int n){ cvt_k<<<(n/2 + 255)/256, 256>>>(s, d, n); };
    CVT(feat,  p_featb,  BN_*DP_);
    CVT(feats, p_featsb, BN_*DP_);
    CVT(fc1w,  pw_fc1,  DP_*DM_);
    CVT(fc1sw, pw_fc1s, DP_*DM_);
    CVT(wk,    pw_wk,   DM_*DM_);
    CVT(wv,    pw_wv,   DM_*DM_);
    CVT(fd2w,  pw_fd2,  DM_*DM_);
    CVT(fg1w,  pw_fg1,  DM_*DM_);
    CVT(fg2w,  pw_fg2,  DM_*DM_);
    CVT(fc2w,  pw_fc2,  DM_*DP_);

    // 1. KNN (exact fp32)
    knn_k<<<dim3(B_, N_/128), 128>>>(xyz, xyzs);

    // 2. q = feat @ fc1 + b ; xs = feats @ fc1s + b
    hgemm_k<false,false,true><<<dim3(BN_/128, 2), 256>>>(p_featb,  DP_, pw_fc1,  DM_, fc1b,  nullptr, p_qb,  BN_);
    hgemm_k<false,false,true><<<dim3(BN_/128, 2), 256>>>(p_featsb, DP_, pw_fc1s, DM_, fc1sb, nullptr, p_xsb, BN_);
    // 3. k_all = xs @ wk ; v_all = xs @ wv
    hgemm_k<false,false,true><<<dim3(BN_/128, 2), 256>>>(p_xsb, DM_, pw_wk, DM_, p_zero, nullptr, p_kb, BN_);
    hgemm_k<false,false,true><<<dim3(BN_/128, 2), 256>>>(p_xsb, DM_, pw_wv, DM_, p_zero, nullptr, p_vb, BN_);
    // 4. fused pos GEMM -> g (bf16), vp (bf16)
    posg_k<<<dim3(BNK_/128, 2), 256>>>(xyz, xyzs, fd1w, fd1b, fd2b);
    // 5. h = relu(g @ fg1 + b)
    hgemm_k<true,false,true><<<dim3(BNK_/128, 2), 256>>>(p_gb, DM_, pw_fg1, DM_, fg1b, nullptr, p_hb, BNK_);
    // 6. a = h @ fg2 + b  (into g_gb)
    hgemm_k<false,false,true><<<dim3(BNK_/128, 2), 256>>>(p_hb, DM_, pw_fg2, DM_, fg2b, nullptr, p_gb, BNK_);
    // 7. softmax over K + reduce with vp -> res (+ attn output)
    smred_k<<<BN_, 256>>>(out_attn, write_attn);
    // 8. out = features + res @ fc2 + b   (fp32 output, fp32 residual add)
    hgemm_k<false,true,false><<<dim3(BN_/128, 1), 256>>>(p_resb, DM_, pw_fc2, DP_, fc2b, feat, out_main, BN_);
}

// round 5
// speedup vs baseline: 1.9100x; 1.5941x over previous
#include <cuda_runtime.h>
#include <cuda_bf16.h>
#include <mma.h>
using namespace nvcuda;

#define B_  8
#define N_  2048
#define M_  2048
#define DP_ 128
#define DM_ 256
#define K_  16
#define BN_  (B_*N_)        // 16384
#define BNK_ (B_*N_*K_)     // 262144

typedef __nv_bfloat16 bf16;
typedef __nv_bfloat162 bf162;

// ---------------- scratch (device globals: allocation-free rule) -------------
__device__ bf16  g_featb [BN_*DP_];
__device__ bf16  g_featsb[BN_*DP_];
__device__ bf16  g_qb [BN_*DM_];
__device__ bf16  g_xsb[BN_*DM_];
__device__ bf16  g_kb [BN_*DM_];
__device__ bf16  g_vb [BN_*DM_];
__device__ bf16  g_gb [(size_t)BNK_*DM_];   // g, later reused for pre-softmax a
__device__ bf16  g_hb [(size_t)BNK_*DM_];
__device__ bf16  g_vpb[(size_t)BNK_*DM_];   // vg + pos
__device__ bf16  g_resb[BN_*DM_];
__device__ float g_outtmp[BN_*DP_];
__device__ int   g_knn [BNK_];
__device__ float g_zerobias[DM_];           // zero-initialized

// bf16 weight copies
__device__ bf16 g_w_fc1 [DP_*DM_];
__device__ bf16 g_w_fc1s[DP_*DM_];
__device__ bf16 g_w_wk  [DM_*DM_];
__device__ bf16 g_w_wv  [DM_*DM_];
__device__ bf16 g_w_fd2 [DM_*DM_];
__device__ bf16 g_w_fg1 [DM_*DM_];
__device__ bf16 g_w_fg2 [DM_*DM_];
__device__ bf16 g_w_fc2 [DM_*DP_];

// ---------------- cp.async helpers -------------------------------------------
__device__ __forceinline__ unsigned saddr(const void* p) {
    return (unsigned)__cvta_generic_to_shared(p);
}
__device__ __forceinline__ void cpa16(unsigned dst, const void* src) {
    asm volatile("cp.async.cg.shared.global [%0], [%1], 16;\n" :: "r"(dst), "l"(src));
}
#define CP_COMMIT()  asm volatile("cp.async.commit_group;\n")
#define CP_WAIT1()   asm volatile("cp.async.wait_group 1;\n")
#define CP_WAIT0()   asm volatile("cp.async.wait_group 0;\n")

// ---------------- fused fp32 -> bf16 convert (all tensors in one launch) -----
struct CvtArgs { const float* s[10]; bf16* d[10]; };
#define CVT_TOTAL 4620288LL
#define CVT_BLOCKS 9024

__global__ void __launch_bounds__(256) cvtall_k(CvtArgs a)
{
    const long long cum[11] = {0LL, 2097152LL, 4194304LL, 4227072LL, 4259840LL,
                               4325376LL, 4390912LL, 4456448LL, 4521984LL,
                               4587520LL, 4620288LL};
    long long p = ((long long)blockIdx.x * 256 + threadIdx.x) * 2;
    if (p >= CVT_TOTAL) return;
    int seg = 0;
    #pragma unroll
    for (int s = 1; s < 10; s++) if (p >= cum[s]) seg = s;
    long long off = p - cum[seg];
    float2 v = *reinterpret_cast<const float2*>(a.s[seg] + off);
    *reinterpret_cast<bf162*>(a.d[seg] + off) = __float22bfloat162_rn(v);
}

// ---------------- KNN: exact expanded-form d2, stable top-16 -----------------
__global__ void __launch_bounds__(128) knn_k(const float* __restrict__ xyz,
                                             const float* __restrict__ xyzs)
{
    __shared__ float sy0[M_], sy1[M_], sy2[M_], syn[M_];
    int b = blockIdx.x;
    int n = blockIdx.y * 128 + threadIdx.x;
    const float* ys = xyzs + (size_t)b * M_ * 3;
    for (int m = threadIdx.x; m < M_; m += 128) {
        float y0 = ys[m*3+0], y1 = ys[m*3+1], y2 = ys[m*3+2];
        sy0[m] = y0; sy1[m] = y1; sy2[m] = y2;
        syn[m] = __fadd_rn(__fadd_rn(__fmul_rn(y0,y0), __fmul_rn(y1,y1)), __fmul_rn(y2,y2));
    }
    __syncthreads();

    const float* x = xyz + ((size_t)b * N_ + n) * 3;
    float x0 = x[0], x1 = x[1], x2 = x[2];
    float xn = __fadd_rn(__fadd_rn(__fmul_rn(x0,x0), __fmul_rn(x1,x1)), __fmul_rn(x2,x2));

    float bd[K_]; int bi[K_];
    #pragma unroll
    for (int k = 0; k < K_; k++) { bd[k] = 3.4e38f; bi[k] = 0; }

    for (int m = 0; m < M_; m++) {
        float dot = __fadd_rn(__fadd_rn(__fmul_rn(x0, sy0[m]), __fmul_rn(x1, sy1[m])),
                              __fmul_rn(x2, sy2[m]));
        float d2 = __fsub_rn(__fadd_rn(xn, syn[m]), __fmul_rn(2.0f, dot));
        if (d2 < bd[K_-1]) {
            int p = K_ - 1;
            while (p > 0 && bd[p-1] > d2) { bd[p] = bd[p-1]; bi[p] = bi[p-1]; p--; }
            bd[p] = d2; bi[p] = m;   // stable: equal keeps earlier (lower) index
        }
    }
    size_t base = ((size_t)b * N_ + n) * K_;
    #pragma unroll
    for (int k = 0; k < K_; k++) g_knn[base + k] = bi[k];
}

// ---------------- bf16 wmma GEMM, double-buffered cp.async pipeline ----------
// block tile 128x128, 8 warps (warp tile 32x64), BK=32
template<bool RELU, bool ADDSRC, bool OUTBF>
__global__ void __launch_bounds__(256, 2)
hgemm_k(const bf16* __restrict__ A, int kd,
        const bf16* __restrict__ W, int wn,
        const float* __restrict__ bias,
        const float* __restrict__ Add,   // fp32 add source (stride wn)
        void* __restrict__ Cout)
{
    __shared__ bf16 As[2][128][40];
    __shared__ bf16 Bs[2][32][136];
    __shared__ float Cs[8][16][20];

    int row0 = blockIdx.x * 128;
    int col0 = blockIdx.y * 128;
    int tid = threadIdx.x;
    int wid = tid >> 5, lane = tid & 31;
    int wr = (wid >> 1) * 32;
    int wc = (wid & 1) * 64;

    wmma::fragment<wmma::accumulator, 16,16,16, float> acc[2][4];
    #pragma unroll
    for (int i=0;i<2;i++)
        #pragma unroll
        for (int j=0;j<4;j++) wmma::fill_fragment(acc[i][j], 0.0f);

    int nk = kd >> 5;

    // stage 0
    {
        #pragma unroll
        for (int i=0;i<2;i++){
            int f = tid + i*256, r = f >> 2, c = (f & 3) * 8;
            cpa16(saddr(&As[0][r][c]), A + (size_t)(row0+r)*kd + c);
        }
        #pragma unroll
        for (int i=0;i<2;i++){
            int f = tid + i*256, r = f >> 4, c = (f & 15) * 8;
            cpa16(saddr(&Bs[0][r][c]), W + (size_t)r*wn + col0 + c);
        }
        CP_COMMIT();
    }

    for (int t = 0; t < nk; t++) {
        if (t + 1 < nk) {
            int nb = (t+1) & 1, k0 = (t+1) << 5;
            #pragma unroll
            for (int i=0;i<2;i++){
                int f = tid + i*256, r = f >> 2, c = (f & 3) * 8;
                cpa16(saddr(&As[nb][r][c]), A + (size_t)(row0+r)*kd + k0 + c);
            }
            #pragma unroll
            for (int i=0;i<2;i++){
                int f = tid + i*256, r = f >> 4, c = (f & 15) * 8;
                cpa16(saddr(&Bs[nb][r][c]), W + (size_t)(k0+r)*wn + col0 + c);
            }
            CP_COMMIT();
            CP_WAIT1();
        } else {
            CP_WAIT0();
        }
        __syncthreads();
        int cb = t & 1;
        #pragma unroll
        for (int kk = 0; kk < 32; kk += 16) {
            wmma::fragment<wmma::matrix_a, 16,16,16, bf16, wmma::row_major> af[2];
            wmma::fragment<wmma::matrix_b, 16,16,16, bf16, wmma::row_major> bfr[4];
            #pragma unroll
            for (int i=0;i<2;i++) wmma::load_matrix_sync(af[i], &As[cb][wr+i*16][kk], 40);
            #pragma unroll
            for (int j=0;j<4;j++) wmma::load_matrix_sync(bfr[j], &Bs[cb][kk][wc+j*16], 136);
            #pragma unroll
            for (int i=0;i<2;i++)
                #pragma unroll
                for (int j=0;j<4;j++)
                    wmma::mma_sync(acc[i][j], af[i], bfr[j], acc[i][j]);
        }
        __syncthreads();
    }

    #pragma unroll
    for (int i=0;i<2;i++)
        #pragma unroll
        for (int j=0;j<4;j++) {
            wmma::store_matrix_sync(&Cs[wid][0][0], acc[i][j], 20, wmma::mem_row_major);
            __syncwarp();
            int rbase = row0 + wr + i*16;
            int cbase = col0 + wc + j*16;
            #pragma unroll
            for (int e=0;e<4;e++){
                int p  = lane*4 + e;
                int rr = p >> 3;
                int cc = (p & 7) * 2;
                float v0 = Cs[wid][rr][cc]   + bias[cbase+cc];
                float v1 = Cs[wid][rr][cc+1] + bias[cbase+cc+1];
                if (RELU){ v0 = fmaxf(v0,0.f); v1 = fmaxf(v1,0.f); }
                size_t off = (size_t)(rbase+rr)*wn + cbase + cc;
                if (ADDSRC){ v0 += Add[off]; v1 += Add[off+1]; }
                if (OUTBF){
                    *reinterpret_cast<bf162*>(reinterpret_cast<bf16*>(Cout) + off) =
                        __float22bfloat162_rn(make_float2(v0,v1));
                } else {
                    *reinterpret_cast<float2*>(reinterpret_cast<float*>(Cout) + off) =
                        make_float2(v0,v1);
                }
            }
            __syncwarp();
        }
}

// ------- fused pos GEMM (bf16 MMA): A = relu(delta@fd1 + b) on the fly -------
// double-buffered: A generated by ALU, B prefetched by cp.async
// epilogue: pos = acc + fd2_b ; g = q - kg + pos ; vp = vg + pos  (both bf16)
__global__ void __launch_bounds__(256, 2)
posg_k(const float* __restrict__ xyz, const float* __restrict__ xyzs,
       const float* __restrict__ fd1w, const float* __restrict__ fd1b,
       const float* __restrict__ fd2b)
{
    __shared__ bf16 As[2][128][40];
    __shared__ bf16 Bs[2][32][136];
    __shared__ float Cs[8][16][20];
    __shared__ float sDel[3][128];
    __shared__ int   sQ[128], sS[128];
    __shared__ float sF0[DM_], sF1[DM_], sF2[DM_], sFb[DM_];

    int row0 = blockIdx.x * 128;
    int col0 = blockIdx.y * 128;
    int tid  = threadIdx.x;
    int wid = tid >> 5, lane = tid & 31;
    int wr = (wid >> 1) * 32;
    int wc = (wid & 1) * 64;

    sF0[tid] = fd1w[tid]; sF1[tid] = fd1w[256+tid]; sF2[tid] = fd1w[512+tid]; sFb[tid] = fd1b[tid];
    if (tid < 128) {
        int r = row0 + tid;
        int b = r >> 15;                 // / (N_*K_)
        int rem = r & 32767;
        int n = rem >> 4;
        int i = g_knn[r];
        sQ[tid] = b * N_ + n;
        sS[tid] = b * M_ + i;
        const float* x = xyz  + ((size_t)b * N_ + n) * 3;
        const float* y = xyzs + ((size_t)b * M_ + i) * 3;
        sDel[0][tid] = x[0]-y[0]; sDel[1][tid] = x[1]-y[1]; sDel[2][tid] = x[2]-y[2];
    }
    // prefetch B stage 0
    #pragma unroll
    for (int i=0;i<2;i++){
        int f = tid + i*256, r = f >> 4, c = (f & 15) * 8;
        cpa16(saddr(&Bs[0][r][c]), g_w_fd2 + (size_t)r*DM_ + col0 + c);
    }
    CP_COMMIT();
    __syncthreads();   // sDel/sF ready for A generation

    // generate A stage 0
    #pragma unroll
    for (int e = 0; e < 16; e++) {
        int f = tid + e * 256;
        int r = f & 127;
        int k = f >> 7;
        float h = fmaf(sDel[0][r], sF0[k],
                  fmaf(sDel[1][r], sF1[k],
                  fmaf(sDel[2][r], sF2[k], sFb[k])));
        As[0][r][k] = __float2bfloat16(fmaxf(h, 0.0f));
    }

    wmma::fragment<wmma::accumulator, 16,16,16, float> acc[2][4];
    #pragma unroll
    for (int i=0;i<2;i++)
        #pragma unroll
        for (int j=0;j<4;j++) wmma::fill_fragment(acc[i][j], 0.0f);

    const int nk = DM_ >> 5;   // 8
    for (int t = 0; t < nk; t++) {
        if (t + 1 < nk) {
            int nb = (t+1) & 1, k0 = (t+1) << 5;
            #pragma unroll
            for (int e = 0; e < 16; e++) {
                int f = tid + e * 256;
                int r = f & 127;
                int k = f >> 7;
                int tc = k0 + k;
                float h = fmaf(sDel[0][r], sF0[tc],
                          fmaf(sDel[1][r], sF1[tc],
                          fmaf(sDel[2][r], sF2[tc], sFb[tc])));
                As[nb][r][k] = __float2bfloat16(fmaxf(h, 0.0f));
            }
            #pragma unroll
            for (int i=0;i<2;i++){
                int f = tid + i*256, r = f >> 4, c = (f & 15) * 8;
                cpa16(saddr(&Bs[nb][r][c]), g_w_fd2 + (size_t)(k0+r)*DM_ + col0 + c);
            }
            CP_COMMIT();
            CP_WAIT1();
        } else {
            CP_WAIT0();
        }
        __syncthreads();
        int cb = t & 1;
        #pragma unroll
        for (int kk = 0; kk < 32; kk += 16) {
            wmma::fragment<wmma::matrix_a, 16,16,16, bf16, wmma::row_major> af[2];
            wmma::fragment<wmma::matrix_b, 16,16,16, bf16, wmma::row_major> bfr[4];
            #pragma unroll
            for (int i=0;i<2;i++) wmma::load_matrix_sync(af[i], &As[cb][wr+i*16][kk], 40);
            #pragma unroll
            for (int j=0;j<4;j++) wmma::load_matrix_sync(bfr[j], &Bs[cb][kk][wc+j*16], 136);
            #pragma unroll
            for (int i=0;i<2;i++)
                #pragma unroll
                for (int j=0;j<4;j++)
                    wmma::mma_sync(acc[i][j], af[i], bfr[j], acc[i][j]);
        }
        __syncthreads();
    }

    #pragma unroll
    for (int i=0;i<2;i++)
        #pragma unroll
        for (int j=0;j<4;j++) {
            wmma::store_matrix_sync(&Cs[wid][0][0], acc[i][j], 20, wmma::mem_row_major);
            __syncwarp();
            int rloc  = wr + i*16;
            int cbase = col0 + wc + j*16;
            #pragma unroll
            for (int e=0;e<4;e++){
                int p  = lane*4 + e;
                int rr = p >> 3;
                int cc = (p & 7) * 2;
                int rl = rloc + rr;
                int r  = row0 + rl;
                float pos0 = Cs[wid][rr][cc]   + fd2b[cbase+cc];
                float pos1 = Cs[wid][rr][cc+1] + fd2b[cbase+cc+1];
                size_t qoff = (size_t)sQ[rl] * DM_ + cbase + cc;
                size_t soff = (size_t)sS[rl] * DM_ + cbase + cc;
                float2 qv = __bfloat1622float2(*reinterpret_cast<const bf162*>(g_qb + qoff));
                float2 kv = __bfloat1622float2(*reinterpret_cast<const bf162*>(g_kb + soff));
                float2 vv = __bfloat1622float2(*reinterpret_cast<const bf162*>(g_vb + soff));
                size_t off = (size_t)r * DM_ + cbase + cc;
                *reinterpret_cast<bf162*>(g_gb + off) =
                    __float22bfloat162_rn(make_float2(qv.x - kv.x + pos0, qv.y - kv.y + pos1));
                *reinterpret_cast<bf162*>(g_vpb + off) =
                    __float22bfloat162_rn(make_float2(vv.x + pos0, vv.y + pos1));
            }
            __syncwarp();
        }
}

// -------- softmax over K (scale 1/16) + weighted reduce over (vg+pos) --------
__global__ void __launch_bounds__(256) smred_k(float* __restrict__ attn_out, int write_attn)
{
    int bn = blockIdx.x;
    int j  = threadIdx.x;
    const bf16* ap  = g_gb  + (size_t)bn * K_ * DM_ + j;   // 'a' lives in g_gb
    const bf16* vpp = g_vpb + (size_t)bn * K_ * DM_ + j;

    float av[K_];
    float mx = -3.4e38f;
    #pragma unroll
    for (int k = 0; k < K_; k++) {
        av[k] = __bfloat162float(ap[k*DM_]) * 0.0625f;
        mx = fmaxf(mx, av[k]);
    }
    float s = 0.0f;
    #pragma unroll
    for (int k = 0; k < K_; k++) { av[k] = expf(av[k] - mx); s += av[k]; }
    float inv = 1.0f / s;
    float res = 0.0f;
    #pragma unroll
    for (int k = 0; k < K_; k++) {
        float a = av[k] * inv;
        if (write_attn) attn_out[((size_t)bn * K_ + k) * DM_ + j] = a;
        res = fmaf(a, __bfloat162float(vpp[k*DM_]), res);
    }
    g_resb[(size_t)bn * DM_ + j] = __float2bfloat16(res);
}

// --------------------------------- launch ------------------------------------
extern "C" void kernel_launch(void* const* d_in, const int* in_sizes, int n_in,
                              void* d_out, int out_size)
{
    const float* xyz   = (const float*)d_in[0];
    const float* feat  = (const float*)d_in[1];
    const float* xyzs  = (const float*)d_in[2];
    const float* feats = (const float*)d_in[3];
    const float* fc1w  = (const float*)d_in[4];
    const float* fc1b  = (const float*)d_in[5];
    const float* fc1sw = (const float*)d_in[6];
    const float* fc1sb = (const float*)d_in[7];
    const float* fc2w  = (const float*)d_in[8];
    const float* fc2b  = (const float*)d_in[9];
    const float* fd1w  = (const float*)d_in[10];
    const float* fd1b  = (const float*)d_in[11];
    const float* fd2w  = (const float*)d_in[12];
    const float* fd2b  = (const float*)d_in[13];
    const float* fg1w  = (const float*)d_in[14];
    const float* fg1b  = (const float*)d_in[15];
    const float* fg2w  = (const float*)d_in[16];
    const float* fg2b  = (const float*)d_in[17];
    const float* wk    = (const float*)d_in[18];
    const float* wv    = (const float*)d_in[19];

    static bool init = false;
    static bf16 *p_featb, *p_featsb, *p_qb, *p_xsb, *p_kb, *p_vb, *p_gb, *p_hb, *p_resb;
    static bf16 *pw_fc1, *pw_fc1s, *pw_wk, *pw_wv, *pw_fd2, *pw_fg1, *pw_fg2, *pw_fc2;
    static float *p_outtmp, *p_zero;
    if (!init) {
        cudaGetSymbolAddress((void**)&p_featb,  g_featb);
        cudaGetSymbolAddress((void**)&p_featsb, g_featsb);
        cudaGetSymbolAddress((void**)&p_qb,  g_qb);
        cudaGetSymbolAddress((void**)&p_xsb, g_xsb);
        cudaGetSymbolAddress((void**)&p_kb,  g_kb);
        cudaGetSymbolAddress((void**)&p_vb,  g_vb);
        cudaGetSymbolAddress((void**)&p_gb,  g_gb);
        cudaGetSymbolAddress((void**)&p_hb,  g_hb);
        cudaGetSymbolAddress((void**)&p_resb, g_resb);
        cudaGetSymbolAddress((void**)&pw_fc1,  g_w_fc1);
        cudaGetSymbolAddress((void**)&pw_fc1s, g_w_fc1s);
        cudaGetSymbolAddress((void**)&pw_wk,   g_w_wk);
        cudaGetSymbolAddress((void**)&pw_wv,   g_w_wv);
        cudaGetSymbolAddress((void**)&pw_fd2,  g_w_fd2);
        cudaGetSymbolAddress((void**)&pw_fg1,  g_w_fg1);
        cudaGetSymbolAddress((void**)&pw_fg2,  g_w_fg2);
        cudaGetSymbolAddress((void**)&pw_fc2,  g_w_fc2);
        cudaGetSymbolAddress((void**)&p_outtmp, g_outtmp);
        cudaGetSymbolAddress((void**)&p_zero,   g_zerobias);
        init = true;
    }

    const long long OUTE  = (long long)BN_ * DP_;     //  2,097,152
    const long long ATTNE = (long long)BNK_ * DM_;    // 67,108,864
    float* out = (float*)d_out;
    float* out_main; float* out_attn; int write_attn;
    if ((long long)out_size >= OUTE + ATTNE) { out_main = out; out_attn = out + OUTE; write_attn = 1; }
    else if ((long long)out_size == ATTNE)   { out_main = p_outtmp; out_attn = out; write_attn = 1; }
    else                                      { out_main = out; out_attn = nullptr; write_attn = 0; }

    // 1. KNN (exact fp32)
    knn_k<<<dim3(B_, N_/128), 128>>>(xyz, xyzs);

    // 2. all fp32->bf16 conversions in ONE launch
    CvtArgs ca;
    ca.s[0]=feat;  ca.d[0]=p_featb;
    ca.s[1]=feats; ca.d[1]=p_featsb;
    ca.s[2]=fc1w;  ca.d[2]=pw_fc1;
    ca.s[3]=fc1sw; ca.d[3]=pw_fc1s;
    ca.s[4]=wk;    ca.d[4]=pw_wk;
    ca.s[5]=wv;    ca.d[5]=pw_wv;
    ca.s[6]=fd2w;  ca.d[6]=pw_fd2;
    ca.s[7]=fg1w;  ca.d[7]=pw_fg1;
    ca.s[8]=fg2w;  ca.d[8]=pw_fg2;
    ca.s[9]=fc2w;  ca.d[9]=pw_fc2;
    cvtall_k<<<CVT_BLOCKS, 256>>>(ca);

    // 3. q = feat @ fc1 + b ; xs = feats @ fc1s + b
    hgemm_k<false,false,true><<<dim3(BN_/128, 2), 256>>>(p_featb,  DP_, pw_fc1,  DM_, fc1b,  nullptr, p_qb);
    hgemm_k<false,false,true><<<dim3(BN_/128, 2), 256>>>(p_featsb, DP_, pw_fc1s, DM_, fc1sb, nullptr, p_xsb);
    // 4. k_all = xs @ wk ; v_all = xs @ wv
    hgemm_k<false,false,true><<<dim3(BN_/128, 2), 256>>>(p_xsb, DM_, pw_wk, DM_, p_zero, nullptr, p_kb);
    hgemm_k<false,false,true><<<dim3(BN_/128, 2), 256>>>(p_xsb, DM_, pw_wv, DM_, p_zero, nullptr, p_vb);
    // 5. fused pos GEMM -> g (bf16), vp (bf16)
    posg_k<<<dim3(BNK_/128, 2), 256>>>(xyz, xyzs, fd1w, fd1b, fd2b);
    // 6. h = relu(g @ fg1 + b)
    hgemm_k<true,false,true><<<dim3(BNK_/128, 2), 256>>>(p_gb, DM_, pw_fg1, DM_, fg1b, nullptr, p_hb);
    // 7. a = h @ fg2 + b  (into g_gb)
    hgemm_k<false,false,true><<<dim3(BNK_/128, 2), 256>>>(p_hb, DM_, pw_fg2, DM_, fg2b, nullptr, p_gb);
    // 8. softmax over K + reduce with vp -> res (+ attn output)
    smred_k<<<BN_, 256>>>(out_attn, write_attn);
    // 9. out = features + res @ fc2 + b   (fp32 output, fp32 residual add)
    hgemm_k<false,true,false><<<dim3(BN_/128, 1), 256>>>(p_resb, DM_, pw_fc2, DP_, fc2b, feat, out_main);
}

// round 9
// speedup vs baseline: 1.9189x; 1.0047x over previous
#include <cuda_runtime.h>
#include <cuda_bf16.h>
#include <mma.h>
#include <cstdint>
using namespace nvcuda;

#define B_  8
#define N_  2048
#define M_  2048
#define DP_ 128
#define DM_ 256
#define K_  16
#define BN_  (B_*N_)        // 16384
#define BNK_ (B_*N_*K_)     // 262144

typedef __nv_bfloat16 bf16;
typedef __nv_bfloat162 bf162;

// ---------------- scratch (device globals: allocation-free rule) -------------
__device__ bf16  g_featb [BN_*DP_];
__device__ bf16  g_featsb[BN_*DP_];
__device__ bf16  g_qb [BN_*DM_];
__device__ bf16  g_xsb[BN_*DM_];
__device__ bf16  g_kb [BN_*DM_];
__device__ bf16  g_vb [BN_*DM_];
__device__ bf16  g_gb [(size_t)BNK_*DM_];   // g, later reused for pre-softmax a
__device__ bf16  g_hb [(size_t)BNK_*DM_];
__device__ bf16  g_vpb[(size_t)BNK_*DM_];   // vg + pos
__device__ bf16  g_resb[BN_*DM_];
__device__ float g_outtmp[BN_*DP_];
__device__ int   g_knn [BNK_];
__device__ float g_zerobias[DM_];           // zero-initialized

// bf16 weight copies (row-major, same layout as fp32 originals)
__device__ bf16 g_w_fc1 [DP_*DM_];
__device__ bf16 g_w_fc1s[DP_*DM_];
__device__ bf16 g_w_wk  [DM_*DM_];
__device__ bf16 g_w_wv  [DM_*DM_];
__device__ bf16 g_w_fd2 [DM_*DM_];
__device__ bf16 g_w_fg1 [DM_*DM_];
__device__ bf16 g_w_fg2 [DM_*DM_];
__device__ bf16 g_w_fc2 [DM_*DP_];

// ---------------- cp.async helpers -------------------------------------------
__device__ __forceinline__ unsigned saddr(const void* p) {
    return (unsigned)__cvta_generic_to_shared(p);
}
__device__ __forceinline__ void cpa16(unsigned dst, const void* src) {
    asm volatile("cp.async.cg.shared.global [%0], [%1], 16;\n" :: "r"(dst), "l"(src));
}
#define CP_COMMIT()  asm volatile("cp.async.commit_group;\n")
#define CP_WAIT1()   asm volatile("cp.async.wait_group 1;\n")
#define CP_WAIT0()   asm volatile("cp.async.wait_group 0;\n")

// ---------------- fused fp32 -> bf16 convert (all tensors in one launch) -----
struct CvtArgs { const float* s[10]; bf16* d[10]; };
#define CVT_TOTAL 4620288LL
#define CVT_BLOCKS 9024

__global__ void __launch_bounds__(256) cvtall_k(CvtArgs a)
{
    const long long cum[11] = {0LL, 2097152LL, 4194304LL, 4227072LL, 4259840LL,
                               4325376LL, 4390912LL, 4456448LL, 4521984LL,
                               4587520LL, 4620288LL};
    long long p = ((long long)blockIdx.x * 256 + threadIdx.x) * 2;
    if (p >= CVT_TOTAL) return;
    int seg = 0;
    #pragma unroll
    for (int s = 1; s < 10; s++) if (p >= cum[s]) seg = s;
    long long off = p - cum[seg];
    float2 v = *reinterpret_cast<const float2*>(a.s[seg] + off);
    *reinterpret_cast<bf162*>(a.d[seg] + off) = __float22bfloat162_rn(v);
}

// ---------------- KNN: exact expanded-form d2, stable top-16 -----------------
__global__ void __launch_bounds__(128) knn_k(const float* __restrict__ xyz,
                                             const float* __restrict__ xyzs)
{
    __shared__ float sy0[M_], sy1[M_], sy2[M_], syn[M_];
    int b = blockIdx.x;
    int n = blockIdx.y * 128 + threadIdx.x;
    const float* ys = xyzs + (size_t)b * M_ * 3;
    for (int m = threadIdx.x; m < M_; m += 128) {
        float y0 = ys[m*3+0], y1 = ys[m*3+1], y2 = ys[m*3+2];
        sy0[m] = y0; sy1[m] = y1; sy2[m] = y2;
        syn[m] = __fadd_rn(__fadd_rn(__fmul_rn(y0,y0), __fmul_rn(y1,y1)), __fmul_rn(y2,y2));
    }
    __syncthreads();

    const float* x = xyz + ((size_t)b * N_ + n) * 3;
    float x0 = x[0], x1 = x[1], x2 = x[2];
    float xn = __fadd_rn(__fadd_rn(__fmul_rn(x0,x0), __fmul_rn(x1,x1)), __fmul_rn(x2,x2));

    float bd[K_]; int bi[K_];
    #pragma unroll
    for (int k = 0; k < K_; k++) { bd[k] = 3.4e38f; bi[k] = 0; }

    for (int m = 0; m < M_; m++) {
        float dot = __fadd_rn(__fadd_rn(__fmul_rn(x0, sy0[m]), __fmul_rn(x1, sy1[m])),
                              __fmul_rn(x2, sy2[m]));
        float d2 = __fsub_rn(__fadd_rn(xn, syn[m]), __fmul_rn(2.0f, dot));
        if (d2 < bd[K_-1]) {
            int p = K_ - 1;
            while (p > 0 && bd[p-1] > d2) { bd[p] = bd[p-1]; bi[p] = bi[p-1]; p--; }
            bd[p] = d2; bi[p] = m;   // stable: equal keeps earlier (lower) index
        }
    }
    size_t base = ((size_t)b * N_ + n) * K_;
    #pragma unroll
    for (int k = 0; k < K_; k++) g_knn[base + k] = bi[k];
}

// ---------------- bf16 wmma GEMM, 3-stage cp.async pipeline ------------------
// block tile 128x128, 8 warps (warp tile 32x64), BK=32, ONE syncthreads/stage
// dynamic smem layout: As[3][128][40] | Bs[3][32][136] | Cs[8][16][20]
#define HG_SMEM (3*10240 + 3*8704 + 10240)   // 67072

template<int KD, bool RELU, bool ADDSRC, bool OUTBF>
__global__ void __launch_bounds__(256, 2)
hgemm_k(const bf16* __restrict__ A,
        const bf16* __restrict__ W, int wn,
        const float* __restrict__ bias,
        const float* __restrict__ Add,   // fp32 add source (stride wn)
        void* __restrict__ Cout)
{
    extern __shared__ __align__(16) char smem[];
    typedef bf16 (*AsT)[128][40];
    typedef bf16 (*BsT)[32][136];
    AsT As = (AsT)(smem);
    BsT Bs = (BsT)(smem + 3*10240);
    float (*Cs)[16][20] = (float(*)[16][20])(smem + 3*10240 + 3*8704);

    const int nk = KD >> 5;
    int row0 = blockIdx.x * 128;
    int col0 = blockIdx.y * 128;
    int tid = threadIdx.x;
    int wid = tid >> 5, lane = tid & 31;
    int wr = (wid >> 1) * 32;
    int wc = (wid & 1) * 64;

    wmma::fragment<wmma::accumulator, 16,16,16, float> acc[2][4];
    #pragma unroll
    for (int i=0;i<2;i++)
        #pragma unroll
        for (int j=0;j<4;j++) wmma::fill_fragment(acc[i][j], 0.0f);

    // prefetch stages 0 and 1
    #pragma unroll
    for (int s = 0; s < 2; s++) {
        int k0 = s << 5;
        #pragma unroll
        for (int i=0;i<2;i++){
            int f = tid + i*256, r = f >> 2, c = (f & 3) * 8;
            cpa16(saddr(&As[s][r][c]), A + (size_t)(row0+r)*KD + k0 + c);
        }
        #pragma unroll
        for (int i=0;i<2;i++){
            int f = tid + i*256, r = f >> 4, c = (f & 15) * 8;
            cpa16(saddr(&Bs[s][r][c]), W + (size_t)(k0+r)*wn + col0 + c);
        }
        CP_COMMIT();
    }

    for (int t = 0; t < nk; t++) {
        if (t + 1 < nk) { CP_WAIT1(); } else { CP_WAIT0(); }
        __syncthreads();                    // stage t ready; stage t-1 reads done
        int cb = t % 3;
        #pragma unroll
        for (int kk = 0; kk < 32; kk += 16) {
            wmma::fragment<wmma::matrix_a, 16,16,16, bf16, wmma::row_major> af[2];
            wmma::fragment<wmma::matrix_b, 16,16,16, bf16, wmma::row_major> bfr[4];
            #pragma unroll
            for (int i=0;i<2;i++) wmma::load_matrix_sync(af[i], &As[cb][wr+i*16][kk], 40);
            #pragma unroll
            for (int j=0;j<4;j++) wmma::load_matrix_sync(bfr[j], &Bs[cb][kk][wc+j*16], 136);
            #pragma unroll
            for (int i=0;i<2;i++)
                #pragma unroll
                for (int j=0;j<4;j++)
                    wmma::mma_sync(acc[i][j], af[i], bfr[j], acc[i][j]);
        }
        if (t + 2 < nk) {                   // prefetch stage t+2 (buffer read at t-1)
            int nb = (t+2) % 3, k0 = (t+2) << 5;
            #pragma unroll
            for (int i=0;i<2;i++){
                int f = tid + i*256, r = f >> 2, c = (f & 3) * 8;
                cpa16(saddr(&As[nb][r][c]), A + (size_t)(row0+r)*KD + k0 + c);
            }
            #pragma unroll
            for (int i=0;i<2;i++){
                int f = tid + i*256, r = f >> 4, c = (f & 15) * 8;
                cpa16(saddr(&Bs[nb][r][c]), W + (size_t)(k0+r)*wn + col0 + c);
            }
            CP_COMMIT();
        }
    }

    #pragma unroll
    for (int i=0;i<2;i++)
        #pragma unroll
        for (int j=0;j<4;j++) {
            wmma::store_matrix_sync(&Cs[wid][0][0], acc[i][j], 20, wmma::mem_row_major);
            __syncwarp();
            int rbase = row0 + wr + i*16;
            int cbase = col0 + wc + j*16;
            #pragma unroll
            for (int e=0;e<4;e++){
                int p  = lane*4 + e;
                int rr = p >> 3;
                int cc = (p & 7) * 2;
                float v0 = Cs[wid][rr][cc]   + bias[cbase+cc];
                float v1 = Cs[wid][rr][cc+1] + bias[cbase+cc+1];
                if (RELU){ v0 = fmaxf(v0,0.f); v1 = fmaxf(v1,0.f); }
                size_t off = (size_t)(rbase+rr)*wn + cbase + cc;
                if (ADDSRC){ v0 += Add[off]; v1 += Add[off+1]; }
                if (OUTBF){
                    *reinterpret_cast<bf162*>(reinterpret_cast<bf16*>(Cout) + off) =
                        __float22bfloat162_rn(make_float2(v0,v1));
                } else {
                    *reinterpret_cast<float2*>(reinterpret_cast<float*>(Cout) + off) =
                        make_float2(v0,v1);
                }
            }
            __syncwarp();
        }
}

// ------- fused pos GEMM (bf16 wmma): A = relu(delta@fd1 + b) generated -------
// A double-buffered (ALU-generated), B on 3-stage cp.async ring, 1 sync/stage
// epilogue: pos = acc + fd2_b ; g = q - kg + pos ; vp = vg + pos  (both bf16)
// dynamic smem: As[2][128][40] | Bs[3][32][136] | Cs[8][16][20] | misc
#define PG_AS    0
#define PG_BS    (2*10240)
#define PG_CS    (PG_BS + 3*8704)
#define PG_MISC  (PG_CS + 10240)
#define PG_SMEM  (PG_MISC + 512*2 + 128*3*4 + 256*4*4)   // 63616

__global__ void __launch_bounds__(256, 2)
posg_k(const float* __restrict__ xyz, const float* __restrict__ xyzs,
       const float* __restrict__ fd1w, const float* __restrict__ fd1b,
       const float* __restrict__ fd2b)
{
    extern __shared__ __align__(16) char smem[];
    typedef bf16 (*AsT)[128][40];
    typedef bf16 (*BsT)[32][136];
    AsT As = (AsT)(smem + PG_AS);
    BsT Bs = (BsT)(smem + PG_BS);
    float (*Cs)[16][20] = (float(*)[16][20])(smem + PG_CS);
    int*   sQ  = (int*)(smem + PG_MISC);
    int*   sS  = sQ + 128;
    float* sD0 = (float*)(sS + 128);
    float* sD1 = sD0 + 128;
    float* sD2 = sD1 + 128;
    float* sF0 = sD2 + 128;
    float* sF1 = sF0 + 256;
    float* sF2 = sF1 + 256;
    float* sFb = sF2 + 256;

    int row0 = blockIdx.x * 128;
    int col0 = blockIdx.y * 128;
    int tid  = threadIdx.x;
    int wid = tid >> 5, lane = tid & 31;
    int wr = (wid >> 1) * 32;
    int wc = (wid & 1) * 64;

    // prefetch B stages 0,1
    #pragma unroll
    for (int s = 0; s < 2; s++) {
        int k0 = s << 5;
        #pragma unroll
        for (int i=0;i<2;i++){
            int f = tid + i*256, r = f >> 4, c = (f & 15) * 8;
            cpa16(saddr(&Bs[s][r][c]), g_w_fd2 + (size_t)(k0+r)*DM_ + col0 + c);
        }
        CP_COMMIT();
    }

    sF0[tid] = fd1w[tid]; sF1[tid] = fd1w[256+tid];
    sF2[tid] = fd1w[512+tid]; sFb[tid] = fd1b[tid];
    if (tid < 128) {
        int r = row0 + tid;
        int b = r >> 15;                 // / (N_*K_)
        int n = (r & 32767) >> 4;
        int i = g_knn[r];
        sQ[tid] = b * N_ + n;
        sS[tid] = b * M_ + i;
        const float* x = xyz  + ((size_t)b * N_ + n) * 3;
        const float* y = xyzs + ((size_t)b * M_ + i) * 3;
        sD0[tid] = x[0]-y[0]; sD1[tid] = x[1]-y[1]; sD2[tid] = x[2]-y[2];
    }
    __syncthreads();     // sDel/sF ready

    // generate A stage 0
    #pragma unroll
    for (int e = 0; e < 16; e++) {
        int f = tid + e * 256;
        int r = f & 127;
        int k = f >> 7;
        float h = fmaf(sD0[r], sF0[k],
                  fmaf(sD1[r], sF1[k],
                  fmaf(sD2[r], sF2[k], sFb[k])));
        As[0][r][k] = __float2bfloat16(fmaxf(h, 0.0f));
    }

    wmma::fragment<wmma::accumulator, 16,16,16, float> acc[2][4];
    #pragma unroll
    for (int i=0;i<2;i++)
        #pragma unroll
        for (int j=0;j<4;j++) wmma::fill_fragment(acc[i][j], 0.0f);

    const int nk = DM_ >> 5;   // 8
    for (int t = 0; t < nk; t++) {
        if (t + 1 < nk) { CP_WAIT1(); } else { CP_WAIT0(); }
        __syncthreads();                    // B(t) ready, genA(t) visible
        int ab = t & 1, bb = t % 3;
        #pragma unroll
        for (int kk = 0; kk < 32; kk += 16) {
            wmma::fragment<wmma::matrix_a, 16,16,16, bf16, wmma::row_major> af[2];
            wmma::fragment<wmma::matrix_b, 16,16,16, bf16, wmma::row_major> bfr[4];
            #pragma unroll
            for (int i=0;i<2;i++) wmma::load_matrix_sync(af[i], &As[ab][wr+i*16][kk], 40);
            #pragma unroll
            for (int j=0;j<4;j++) wmma::load_matrix_sync(bfr[j], &Bs[bb][kk][wc+j*16], 136);
            #pragma unroll
            for (int i=0;i<2;i++)
                #pragma unroll
                for (int j=0;j<4;j++)
                    wmma::mma_sync(acc[i][j], af[i], bfr[j], acc[i][j]);
        }
        if (t + 2 < nk) {
            int nb = (t+2) % 3, k0 = (t+2) << 5;
            #pragma unroll
            for (int i=0;i<2;i++){
                int f = tid + i*256, r = f >> 4, c = (f & 15) * 8;
                cpa16(saddr(&Bs[nb][r][c]), g_w_fd2 + (size_t)(k0+r)*DM_ + col0 + c);
            }
            CP_COMMIT();
        }
        if (t + 1 < nk) {                  // generate A(t+1) into other buffer
            int nb = (t+1) & 1, k0 = (t+1) << 5;
            #pragma unroll
            for (int e = 0; e < 16; e++) {
                int f = tid + e * 256;
                int r = f & 127;
                int k = f >> 7;
                int tc = k0 + k;
                float h = fmaf(sD0[r], sF0[tc],
                          fmaf(sD1[r], sF1[tc],
                          fmaf(sD2[r], sF2[tc], sFb[tc])));
                As[nb][r][k] = __float2bfloat16(fmaxf(h, 0.0f));
            }
        }
    }

    #pragma unroll
    for (int i=0;i<2;i++)
        #pragma unroll
        for (int j=0;j<4;j++) {
            wmma::store_matrix_sync(&Cs[wid][0][0], acc[i][j], 20, wmma::mem_row_major);
            __syncwarp();
            int rloc  = wr + i*16;
            int cbase = col0 + wc + j*16;
            #pragma unroll
            for (int e=0;e<4;e++){
                int p  = lane*4 + e;
                int rr = p >> 3;
                int cc = (p & 7) * 2;
                int rl = rloc + rr;
                int r  = row0 + rl;
                float pos0 = Cs[wid][rr][cc]   + fd2b[cbase+cc];
                float pos1 = Cs[wid][rr][cc+1] + fd2b[cbase+cc+1];
                size_t qoff = (size_t)sQ[rl] * DM_ + cbase + cc;
                size_t soff = (size_t)sS[rl] * DM_ + cbase + cc;
                float2 qv = __bfloat1622float2(*reinterpret_cast<const bf162*>(g_qb + qoff));
                float2 kv = __bfloat1622float2(*reinterpret_cast<const bf162*>(g_kb + soff));
                float2 vv = __bfloat1622float2(*reinterpret_cast<const bf162*>(g_vb + soff));
                size_t off = (size_t)r * DM_ + cbase + cc;
                *reinterpret_cast<bf162*>(g_gb + off) =
                    __float22bfloat162_rn(make_float2(qv.x - kv.x + pos0, qv.y - kv.y + pos1));
                *reinterpret_cast<bf162*>(g_vpb + off) =
                    __float22bfloat162_rn(make_float2(vv.x + pos0, vv.y + pos1));
            }
            __syncwarp();
        }
}

// -------- softmax over K (scale 1/16) + weighted reduce over (vg+pos) --------
__global__ void __launch_bounds__(256) smred_k(float* __restrict__ attn_out, int write_attn)
{
    int bn = blockIdx.x;
    int j  = threadIdx.x;
    const bf16* ap  = g_gb  + (size_t)bn * K_ * DM_ + j;
    const bf16* vpp = g_vpb + (size_t)bn * K_ * DM_ + j;

    float av[K_];
    float mx = -3.4e38f;
    #pragma unroll
    for (int k = 0; k < K_; k++) {
        av[k] = __bfloat162float(ap[k*DM_]) * 0.0625f;
        mx = fmaxf(mx, av[k]);
    }
    float s = 0.0f;
    #pragma unroll
    for (int k = 0; k < K_; k++) { av[k] = expf(av[k] - mx); s += av[k]; }
    float inv = 1.0f / s;
    float res = 0.0f;
    #pragma unroll
    for (int k = 0; k < K_; k++) {
        float a = av[k] * inv;
        if (write_attn) attn_out[((size_t)bn * K_ + k) * DM_ + j] = a;
        res = fmaf(a, __bfloat162float(vpp[k*DM_]), res);
    }
    g_resb[(size_t)bn * DM_ + j] = __float2bfloat16(res);
}

// --------------------------------- launch ------------------------------------
extern "C" void kernel_launch(void* const* d_in, const int* in_sizes, int n_in,
                              void* d_out, int out_size)
{
    const float* xyz   = (const float*)d_in[0];
    const float* feat  = (const float*)d_in[1];
    const float* xyzs  = (const float*)d_in[2];
    const float* feats = (const float*)d_in[3];
    const float* fc1w  = (const float*)d_in[4];
    const float* fc1b  = (const float*)d_in[5];
    const float* fc1sw = (const float*)d_in[6];
    const float* fc1sb = (const float*)d_in[7];
    const float* fc2w  = (const float*)d_in[8];
    const float* fc2b  = (const float*)d_in[9];
    const float* fd1w  = (const float*)d_in[10];
    const float* fd1b  = (const float*)d_in[11];
    const float* fd2w  = (const float*)d_in[12];
    const float* fd2b  = (const float*)d_in[13];
    const float* fg1w  = (const float*)d_in[14];
    const float* fg1b  = (const float*)d_in[15];
    const float* fg2w  = (const float*)d_in[16];
    const float* fg2b  = (const float*)d_in[17];
    const float* wk    = (const float*)d_in[18];
    const float* wv    = (const float*)d_in[19];

    static bool init = false;
    static bf16 *p_featb, *p_featsb, *p_qb, *p_xsb, *p_kb, *p_vb, *p_gb, *p_hb, *p_resb;
    static bf16 *pw_fc1, *pw_fc1s, *pw_wk, *pw_wv, *pw_fg1, *pw_fg2, *pw_fc2;
    static float *p_outtmp, *p_zero;
    if (!init) {
        cudaGetSymbolAddress((void**)&p_featb,  g_featb);
        cudaGetSymbolAddress((void**)&p_featsb, g_featsb);
        cudaGetSymbolAddress((void**)&p_qb,  g_qb);
        cudaGetSymbolAddress((void**)&p_xsb, g_xsb);
        cudaGetSymbolAddress((void**)&p_kb,  g_kb);
        cudaGetSymbolAddress((void**)&p_vb,  g_vb);
        cudaGetSymbolAddress((void**)&p_gb,  g_gb);
        cudaGetSymbolAddress((void**)&p_hb,  g_hb);
        cudaGetSymbolAddress((void**)&p_resb, g_resb);
        cudaGetSymbolAddress((void**)&pw_fc1,  g_w_fc1);
        cudaGetSymbolAddress((void**)&pw_fc1s, g_w_fc1s);
        cudaGetSymbolAddress((void**)&pw_wk,   g_w_wk);
        cudaGetSymbolAddress((void**)&pw_wv,   g_w_wv);
        cudaGetSymbolAddress((void**)&pw_fg1,  g_w_fg1);
        cudaGetSymbolAddress((void**)&pw_fg2,  g_w_fg2);
        cudaGetSymbolAddress((void**)&pw_fc2,  g_w_fc2);
        cudaGetSymbolAddress((void**)&p_outtmp, g_outtmp);
        cudaGetSymbolAddress((void**)&p_zero,   g_zerobias);

        cudaFuncSetAttribute(hgemm_k<128,false,false,true>,
                             cudaFuncAttributeMaxDynamicSharedMemorySize, HG_SMEM);
        cudaFuncSetAttribute(hgemm_k<256,false,false,true>,
                             cudaFuncAttributeMaxDynamicSharedMemorySize, HG_SMEM);
        cudaFuncSetAttribute(hgemm_k<256,true,false,true>,
                             cudaFuncAttributeMaxDynamicSharedMemorySize, HG_SMEM);
        cudaFuncSetAttribute(hgemm_k<256,false,true,false>,
                             cudaFuncAttributeMaxDynamicSharedMemorySize, HG_SMEM);
        cudaFuncSetAttribute(posg_k,
                             cudaFuncAttributeMaxDynamicSharedMemorySize, PG_SMEM);
        init = true;
    }

    const long long OUTE  = (long long)BN_ * DP_;     //  2,097,152
    const long long ATTNE = (long long)BNK_ * DM_;    // 67,108,864
    float* out = (float*)d_out;
    float* out_main; float* out_attn; int write_attn;
    if ((long long)out_size >= OUTE + ATTNE) { out_main = out; out_attn = out + OUTE; write_attn = 1; }
    else if ((long long)out_size == ATTNE)   { out_main = p_outtmp; out_attn = out; write_attn = 1; }
    else                                      { out_main = out; out_attn = nullptr; write_attn = 0; }

    // 1. KNN (exact fp32)
    knn_k<<<dim3(B_, N_/128), 128>>>(xyz, xyzs);

    // 2. all fp32->bf16 conversions in ONE launch
    CvtArgs ca;
    ca.s[0]=feat;  ca.d[0]=p_featb;
    ca.s[1]=feats; ca.d[1]=p_featsb;
    ca.s[2]=fc1w;  ca.d[2]=pw_fc1;
    ca.s[3]=fc1sw; ca.d[3]=pw_fc1s;
    ca.s[4]=wk;    ca.d[4]=pw_wk;
    ca.s[5]=wv;    ca.d[5]=pw_wv;
    ca.s[6]=fd2w;  ca.d[6]=(bf16*)g_w_fd2;   // device-symbol address needed below
    ca.s[7]=fg1w;  ca.d[7]=pw_fg1;
    ca.s[8]=fg2w;  ca.d[8]=pw_fg2;
    ca.s[9]=fc2w;  ca.d[9]=pw_fc2;
    {   // fd2 needs its real device address too
        static bf16* pw_fd2 = nullptr;
        if (!pw_fd2) cudaGetSymbolAddress((void**)&pw_fd2, g_w_fd2);
        ca.d[6] = pw_fd2;
    }
    cvtall_k<<<CVT_BLOCKS, 256>>>(ca);

    // 3. q = feat @ fc1 + b ; xs = feats @ fc1s + b
    hgemm_k<128,false,false,true><<<dim3(BN_/128, 2), 256, HG_SMEM>>>(p_featb,  pw_fc1,  DM_, fc1b,  nullptr, p_qb);
    hgemm_k<128,false,false,true><<<dim3(BN_/128, 2), 256, HG_SMEM>>>(p_featsb, pw_fc1s, DM_, fc1sb, nullptr, p_xsb);
    // 4. k_all = xs @ wk ; v_all = xs @ wv
    hgemm_k<256,false,false,true><<<dim3(BN_/128, 2), 256, HG_SMEM>>>(p_xsb, pw_wk, DM_, p_zero, nullptr, p_kb);
    hgemm_k<256,false,false,true><<<dim3(BN_/128, 2), 256, HG_SMEM>>>(p_xsb, pw_wv, DM_, p_zero, nullptr, p_vb);
    // 5. fused pos GEMM -> g (bf16), vp (bf16)
    posg_k<<<dim3(BNK_/128, 2), 256, PG_SMEM>>>(xyz, xyzs, fd1w, fd1b, fd2b);
    // 6. h = relu(g @ fg1 + b)
    hgemm_k<256,true,false,true><<<dim3(BNK_/128, 2), 256, HG_SMEM>>>(p_gb, pw_fg1, DM_, fg1b, nullptr, p_hb);
    // 7. a = h @ fg2 + b  (into g_gb)
    hgemm_k<256,false,false,true><<<dim3(BNK_/128, 2), 256, HG_SMEM>>>(p_hb, pw_fg2, DM_, fg2b, nullptr, p_gb);
    // 8. softmax over K + reduce with vp -> res (+ attn output)
    smred_k<<<BN_, 256>>>(out_attn, write_attn);
    // 9. out = features + res @ fc2 + b   (fp32 output, fp32 residual add)
    hgemm_k<256,false,true,false><<<dim3(BN_/128, 1), 256, HG_SMEM>>>(p_resb, pw_fc2, DP_, fc2b, feat, out_main);
}

// round 14
// speedup vs baseline: 1.9640x; 1.0235x over previous
#include <cuda_runtime.h>
#include <cuda_bf16.h>
#include <mma.h>
#include <cstdint>
using namespace nvcuda;

#define B_  8
#define N_  2048
#define M_  2048
#define DP_ 128
#define DM_ 256
#define K_  16
#define BN_  (B_*N_)        // 16384
#define BNK_ (B_*N_*K_)     // 262144

typedef __nv_bfloat16 bf16;
typedef __nv_bfloat162 bf162;

// ---------------- scratch (device globals: allocation-free rule) -------------
__device__ bf16  g_featb [BN_*DP_];
__device__ bf16  g_featsb[BN_*DP_];
__device__ bf16  g_qb [BN_*DM_];
__device__ bf16  g_xsb[BN_*DM_];
__device__ bf16  g_kb [BN_*DM_];
__device__ bf16  g_vb [BN_*DM_];
__device__ bf16  g_gb [(size_t)BNK_*DM_];   // g
__device__ bf16  g_hb [(size_t)BNK_*DM_];   // relu(g@fg1+b)
__device__ bf16  g_vpb[(size_t)BNK_*DM_];   // vg + pos
__device__ bf16  g_resb[BN_*DM_];
__device__ float g_outtmp[BN_*DP_];
__device__ int   g_knn [BNK_];
__device__ float g_zerobias[DM_];           // zero-initialized

// bf16 weight copies (row-major, same layout as fp32 originals)
__device__ bf16 g_w_fc1 [DP_*DM_];
__device__ bf16 g_w_fc1s[DP_*DM_];
__device__ bf16 g_w_wk  [DM_*DM_];
__device__ bf16 g_w_wv  [DM_*DM_];
__device__ bf16 g_w_fd2 [DM_*DM_];
__device__ bf16 g_w_fg1 [DM_*DM_];
__device__ bf16 g_w_fg2 [DM_*DM_];
__device__ bf16 g_w_fc2 [DM_*DP_];

// ---------------- cp.async helpers -------------------------------------------
__device__ __forceinline__ unsigned saddr(const void* p) {
    return (unsigned)__cvta_generic_to_shared(p);
}
__device__ __forceinline__ void cpa16(unsigned dst, const void* src) {
    asm volatile("cp.async.cg.shared.global [%0], [%1], 16;\n" :: "r"(dst), "l"(src));
}
#define CP_COMMIT()  asm volatile("cp.async.commit_group;\n")
#define CP_WAIT1()   asm volatile("cp.async.wait_group 1;\n")
#define CP_WAIT0()   asm volatile("cp.async.wait_group 0;\n")

// ---------------- fused fp32 -> bf16 convert ---------------------------------
struct CvtArgs { const float* s[10]; bf16* d[10]; };
#define CVT_TOTAL 4620288LL
#define CVT_BLOCKS 9024

__global__ void __launch_bounds__(256) cvtall_k(CvtArgs a)
{
    const long long cum[11] = {0LL, 2097152LL, 4194304LL, 4227072LL, 4259840LL,
                               4325376LL, 4390912LL, 4456448LL, 4521984LL,
                               4587520LL, 4620288LL};
    long long p = ((long long)blockIdx.x * 256 + threadIdx.x) * 2;
    if (p >= CVT_TOTAL) return;
    int seg = 0;
    #pragma unroll
    for (int s = 1; s < 10; s++) if (p >= cum[s]) seg = s;
    long long off = p - cum[seg];
    float2 v = *reinterpret_cast<const float2*>(a.s[seg] + off);
    *reinterpret_cast<bf162*>(a.d[seg] + off) = __float22bfloat162_rn(v);
}

// ---------------- KNN: exact expanded-form d2, stable top-16 -----------------
__global__ void __launch_bounds__(128) knn_k(const float* __restrict__ xyz,
                                             const float* __restrict__ xyzs)
{
    __shared__ float sy0[M_], sy1[M_], sy2[M_], syn[M_];
    int b = blockIdx.x;
    int n = blockIdx.y * 128 + threadIdx.x;
    const float* ys = xyzs + (size_t)b * M_ * 3;
    for (int m = threadIdx.x; m < M_; m += 128) {
        float y0 = ys[m*3+0], y1 = ys[m*3+1], y2 = ys[m*3+2];
        sy0[m] = y0; sy1[m] = y1; sy2[m] = y2;
        syn[m] = __fadd_rn(__fadd_rn(__fmul_rn(y0,y0), __fmul_rn(y1,y1)), __fmul_rn(y2,y2));
    }
    __syncthreads();

    const float* x = xyz + ((size_t)b * N_ + n) * 3;
    float x0 = x[0], x1 = x[1], x2 = x[2];
    float xn = __fadd_rn(__fadd_rn(__fmul_rn(x0,x0), __fmul_rn(x1,x1)), __fmul_rn(x2,x2));

    float bd[K_]; int bi[K_];
    #pragma unroll
    for (int k = 0; k < K_; k++) { bd[k] = 3.4e38f; bi[k] = 0; }

    for (int m = 0; m < M_; m++) {
        float dot = __fadd_rn(__fadd_rn(__fmul_rn(x0, sy0[m]), __fmul_rn(x1, sy1[m])),
                              __fmul_rn(x2, sy2[m]));
        float d2 = __fsub_rn(__fadd_rn(xn, syn[m]), __fmul_rn(2.0f, dot));
        if (d2 < bd[K_-1]) {
            int p = K_ - 1;
            while (p > 0 && bd[p-1] > d2) { bd[p] = bd[p-1]; bi[p] = bi[p-1]; p--; }
            bd[p] = d2; bi[p] = m;
        }
    }
    size_t base = ((size_t)b * N_ + n) * K_;
    #pragma unroll
    for (int k = 0; k < K_; k++) g_knn[base + k] = bi[k];
}

// ---------------- bf16 wmma GEMM, block tile 128 x BNT, 3-stage pipeline -----
// BNT=256: 8 warps as 2x4, warp tile 64x64 (acc 4x4)
// BNT=128: 8 warps as 4x2, warp tile 32x64 (acc 2x4)
// smem: As[3][128][40] | Bs[3][32][BNT+8] | Cs[8][16][20]
#define HG_SMEM(BNT) (30720 + 3*32*((BNT)+8)*2 + 10240)

template<int KD, int BNT, bool RELU, bool ADDSRC, bool OUTBF>
__global__ void __launch_bounds__(256, 1)
hgemm_k(const bf16* __restrict__ A,
        const bf16* __restrict__ W, int wn,
        const float* __restrict__ bias,
        const float* __restrict__ Add,   // fp32 add source (stride wn)
        void* __restrict__ Cout)
{
    extern __shared__ __align__(16) char smem[];
    constexpr int SB  = BNT + 8;
    constexpr int WRN = (BNT == 256) ? 4 : 2;
    typedef bf16 (*AsT)[128][40];
    AsT As = (AsT)smem;
    bf16* Bs = (bf16*)(smem + 30720);
    float (*Cs)[16][20] = (float(*)[16][20])(smem + 30720 + 3*32*SB*2);

    const int nk = KD >> 5;
    int row0 = blockIdx.x * 128;
    int tid = threadIdx.x;
    int wid = tid >> 5, lane = tid & 31;
    int wr = (BNT == 256) ? (wid >> 2) * 64 : (wid >> 1) * 32;
    int wc = (BNT == 256) ? (wid & 3) * 64 : (wid & 1) * 64;

    wmma::fragment<wmma::accumulator, 16,16,16, float> acc[WRN][4];
    #pragma unroll
    for (int i=0;i<WRN;i++)
        #pragma unroll
        for (int j=0;j<4;j++) wmma::fill_fragment(acc[i][j], 0.0f);

    // prefetch stages 0,1
    #pragma unroll
    for (int s = 0; s < 2; s++) {
        int k0 = s << 5;
        #pragma unroll
        for (int i=0;i<2;i++){
            int f = tid + i*256, r = f >> 2, c = (f & 3) * 8;
            cpa16(saddr(&As[s][r][c]), A + (size_t)(row0+r)*KD + k0 + c);
        }
        #pragma unroll
        for (int i=0;i<BNT/64;i++){
            int f = tid + i*256;
            int r = f / (BNT/8), c = (f % (BNT/8)) * 8;
            cpa16(saddr(Bs + s*32*SB + r*SB + c), W + (size_t)(k0+r)*wn + c);
        }
        CP_COMMIT();
    }

    for (int t = 0; t < nk; t++) {
        if (t + 1 < nk) { CP_WAIT1(); } else { CP_WAIT0(); }
        __syncthreads();
        int cb = t % 3;
        #pragma unroll
        for (int kk = 0; kk < 32; kk += 16) {
            wmma::fragment<wmma::matrix_a, 16,16,16, bf16, wmma::row_major> af[WRN];
            wmma::fragment<wmma::matrix_b, 16,16,16, bf16, wmma::row_major> bfr[4];
            #pragma unroll
            for (int i=0;i<WRN;i++) wmma::load_matrix_sync(af[i], &As[cb][wr+i*16][kk], 40);
            #pragma unroll
            for (int j=0;j<4;j++)
                wmma::load_matrix_sync(bfr[j], Bs + cb*32*SB + kk*SB + wc + j*16, SB);
            #pragma unroll
            for (int i=0;i<WRN;i++)
                #pragma unroll
                for (int j=0;j<4;j++)
                    wmma::mma_sync(acc[i][j], af[i], bfr[j], acc[i][j]);
        }
        if (t + 2 < nk) {
            int nb = (t+2) % 3, k0 = (t+2) << 5;
            #pragma unroll
            for (int i=0;i<2;i++){
                int f = tid + i*256, r = f >> 2, c = (f & 3) * 8;
                cpa16(saddr(&As[nb][r][c]), A + (size_t)(row0+r)*KD + k0 + c);
            }
            #pragma unroll
            for (int i=0;i<BNT/64;i++){
                int f = tid + i*256;
                int r = f / (BNT/8), c = (f % (BNT/8)) * 8;
                cpa16(saddr(Bs + nb*32*SB + r*SB + c), W + (size_t)(k0+r)*wn + c);
            }
            CP_COMMIT();
        }
    }

    #pragma unroll
    for (int i=0;i<WRN;i++)
        #pragma unroll
        for (int j=0;j<4;j++) {
            wmma::store_matrix_sync(&Cs[wid][0][0], acc[i][j], 20, wmma::mem_row_major);
            __syncwarp();
            int rbase = row0 + wr + i*16;
            int cbase = wc + j*16;
            #pragma unroll
            for (int e=0;e<4;e++){
                int p  = lane*4 + e;
                int rr = p >> 3;
                int cc = (p & 7) * 2;
                float v0 = Cs[wid][rr][cc]   + bias[cbase+cc];
                float v1 = Cs[wid][rr][cc+1] + bias[cbase+cc+1];
                if (RELU){ v0 = fmaxf(v0,0.f); v1 = fmaxf(v1,0.f); }
                size_t off = (size_t)(rbase+rr)*wn + cbase + cc;
                if (ADDSRC){ v0 += Add[off]; v1 += Add[off+1]; }
                if (OUTBF){
                    *reinterpret_cast<bf162*>(reinterpret_cast<bf16*>(Cout) + off) =
                        __float22bfloat162_rn(make_float2(v0,v1));
                } else {
                    *reinterpret_cast<float2*>(reinterpret_cast<float*>(Cout) + off) =
                        make_float2(v0,v1);
                }
            }
            __syncwarp();
        }
}

// ---------------- fused a=h@fg2+b -> softmax(K) -> res reduce ----------------
// block tile 128x256 (8 complete bn groups per CTA), same mainloop as hgemm<256,256>
// smem: As[3][128][40] | Bs[3][32][264] | Cs[8][16][20] | aS[128][264] bf16
#define AT_SMEM (30720 + 50688 + 10240 + 67584)   // 159232

__global__ void __launch_bounds__(256, 1)
attn_k(const bf16* __restrict__ A,          // g_hb
       const bf16* __restrict__ W,          // g_w_fg2
       const float* __restrict__ bias,      // fg2b
       float* __restrict__ attn_out, int write_attn)
{
    extern __shared__ __align__(16) char smem[];
    constexpr int SB = 264;
    typedef bf16 (*AsT)[128][40];
    AsT As = (AsT)smem;
    bf16* Bs = (bf16*)(smem + 30720);
    float (*Cs)[16][20] = (float(*)[16][20])(smem + 30720 + 50688);
    bf16* aS = (bf16*)(smem + 30720 + 50688 + 10240);

    const int nk = 8;   // KD=256
    int row0 = blockIdx.x * 128;
    int tid = threadIdx.x;
    int wid = tid >> 5, lane = tid & 31;
    int wr = (wid >> 2) * 64;
    int wc = (wid & 3) * 64;

    wmma::fragment<wmma::accumulator, 16,16,16, float> acc[4][4];
    #pragma unroll
    for (int i=0;i<4;i++)
        #pragma unroll
        for (int j=0;j<4;j++) wmma::fill_fragment(acc[i][j], 0.0f);

    #pragma unroll
    for (int s = 0; s < 2; s++) {
        int k0 = s << 5;
        #pragma unroll
        for (int i=0;i<2;i++){
            int f = tid + i*256, r = f >> 2, c = (f & 3) * 8;
            cpa16(saddr(&As[s][r][c]), A + (size_t)(row0+r)*DM_ + k0 + c);
        }
        #pragma unroll
        for (int i=0;i<4;i++){
            int f = tid + i*256, r = f >> 5, c = (f & 31) * 8;
            cpa16(saddr(Bs + s*32*SB + r*SB + c), W + (size_t)(k0+r)*DM_ + c);
        }
        CP_COMMIT();
    }

    for (int t = 0; t < nk; t++) {
        if (t + 1 < nk) { CP_WAIT1(); } else { CP_WAIT0(); }
        __syncthreads();
        int cb = t % 3;
        #pragma unroll
        for (int kk = 0; kk < 32; kk += 16) {
            wmma::fragment<wmma::matrix_a, 16,16,16, bf16, wmma::row_major> af[4];
            wmma::fragment<wmma::matrix_b, 16,16,16, bf16, wmma::row_major> bfr[4];
            #pragma unroll
            for (int i=0;i<4;i++) wmma::load_matrix_sync(af[i], &As[cb][wr+i*16][kk], 40);
            #pragma unroll
            for (int j=0;j<4;j++)
                wmma::load_matrix_sync(bfr[j], Bs + cb*32*SB + kk*SB + wc + j*16, SB);
            #pragma unroll
            for (int i=0;i<4;i++)
                #pragma unroll
                for (int j=0;j<4;j++)
                    wmma::mma_sync(acc[i][j], af[i], bfr[j], acc[i][j]);
        }
        if (t + 2 < nk) {
            int nb = (t+2) % 3, k0 = (t+2) << 5;
            #pragma unroll
            for (int i=0;i<2;i++){
                int f = tid + i*256, r = f >> 2, c = (f & 3) * 8;
                cpa16(saddr(&As[nb][r][c]), A + (size_t)(row0+r)*DM_ + k0 + c);
            }
            #pragma unroll
            for (int i=0;i<4;i++){
                int f = tid + i*256, r = f >> 5, c = (f & 31) * 8;
                cpa16(saddr(Bs + nb*32*SB + r*SB + c), W + (size_t)(k0+r)*DM_ + c);
            }
            CP_COMMIT();
        }
    }

    // stage a (bias added, bf16 — identical rounding to previous g_gb path)
    #pragma unroll
    for (int i=0;i<4;i++)
        #pragma unroll
        for (int j=0;j<4;j++) {
            wmma::store_matrix_sync(&Cs[wid][0][0], acc[i][j], 20, wmma::mem_row_major);
            __syncwarp();
            int rloc  = wr + i*16;
            int cbase = wc + j*16;
            #pragma unroll
            for (int e=0;e<4;e++){
                int p  = lane*4 + e;
                int rr = p >> 3;
                int cc = (p & 7) * 2;
                float v0 = Cs[wid][rr][cc]   + bias[cbase+cc];
                float v1 = Cs[wid][rr][cc+1] + bias[cbase+cc+1];
                *reinterpret_cast<bf162*>(&aS[(size_t)(rloc+rr)*SB + cbase + cc]) =
                    __float22bfloat162_rn(make_float2(v0, v1));
            }
            __syncwarp();
        }
    __syncthreads();

    // softmax over K=16 within each of the 8 bn groups; reduce with vp
    int f = tid;                       // 0..255 = feature column
    #pragma unroll
    for (int g = 0; g < 8; g++) {
        int bn = blockIdx.x * 8 + g;
        float av[K_];
        float mx = -3.4e38f;
        #pragma unroll
        for (int k = 0; k < K_; k++) {
            av[k] = __bfloat162float(aS[(size_t)(g*16+k)*SB + f]) * 0.0625f;
            mx = fmaxf(mx, av[k]);
        }
        float s = 0.0f;
        #pragma unroll
        for (int k = 0; k < K_; k++) { av[k] = expf(av[k] - mx); s += av[k]; }
        float inv = 1.0f / s;
        float res = 0.0f;
        const bf16* vpp = g_vpb + (size_t)bn * K_ * DM_ + f;
        #pragma unroll
        for (int k = 0; k < K_; k++) {
            float a = av[k] * inv;
            if (write_attn) attn_out[((size_t)bn * K_ + k) * DM_ + f] = a;
            res = fmaf(a, __bfloat162float(vpp[k*DM_]), res);
        }
        g_resb[(size_t)bn * DM_ + f] = __float2bfloat16(res);
    }
}

// ------- fused pos GEMM, block tile 128x256: A = relu(delta@fd1+b) generated -
// epilogue: pos = acc + fd2_b ; g = q - kg + pos ; vp = vg + pos  (both bf16)
// smem: As2[2][128][40] | Bs[3][32][264] | Cs[8][16][20] | misc
#define PG_BS    20480
#define PG_CS    (PG_BS + 50688)
#define PG_MISC  (PG_CS + 10240)
#define PG_SMEM  (PG_MISC + 1024 + 1536 + 4096)   // 88064

__global__ void __launch_bounds__(256, 1)
posg_k(const float* __restrict__ xyz, const float* __restrict__ xyzs,
       const float* __restrict__ fd1w, const float* __restrict__ fd1b,
       const float* __restrict__ fd2b)
{
    extern __shared__ __align__(16) char smem[];
    constexpr int SB = 264;
    typedef bf16 (*AsT)[128][40];
    AsT As = (AsT)smem;
    bf16* Bs = (bf16*)(smem + PG_BS);
    float (*Cs)[16][20] = (float(*)[16][20])(smem + PG_CS);
    int*   sQ  = (int*)(smem + PG_MISC);
    int*   sS  = sQ + 128;
    float* sD0 = (float*)(sS + 128);
    float* sD1 = sD0 + 128;
    float* sD2 = sD1 + 128;
    float* sF0 = sD2 + 128;
    float* sF1 = sF0 + 256;
    float* sF2 = sF1 + 256;
    float* sFb = sF2 + 256;

    int row0 = blockIdx.x * 128;
    int tid  = threadIdx.x;
    int wid = tid >> 5, lane = tid & 31;
    int wr = (wid >> 2) * 64;
    int wc = (wid & 3) * 64;

    // prefetch B stages 0,1 (full-width fd2 weight rows)
    #pragma unroll
    for (int s = 0; s < 2; s++) {
        int k0 = s << 5;
        #pragma unroll
        for (int i=0;i<4;i++){
            int f = tid + i*256, r = f >> 5, c = (f & 31) * 8;
            cpa16(saddr(Bs + s*32*SB + r*SB + c), g_w_fd2 + (size_t)(k0+r)*DM_ + c);
        }
        CP_COMMIT();
    }

    sF0[tid] = fd1w[tid]; sF1[tid] = fd1w[256+tid];
    sF2[tid] = fd1w[512+tid]; sFb[tid] = fd1b[tid];
    if (tid < 128) {
        int r = row0 + tid;
        int b = r >> 15;                 // / (N_*K_)
        int n = (r & 32767) >> 4;
        int i = g_knn[r];
        sQ[tid] = b * N_ + n;
        sS[tid] = b * M_ + i;
        const float* x = xyz  + ((size_t)b * N_ + n) * 3;
        const float* y = xyzs + ((size_t)b * M_ + i) * 3;
        sD0[tid] = x[0]-y[0]; sD1[tid] = x[1]-y[1]; sD2[tid] = x[2]-y[2];
    }
    __syncthreads();     // sDel/sF ready

    // generate A stage 0
    #pragma unroll
    for (int e = 0; e < 16; e++) {
        int f = tid + e * 256;
        int r = f & 127;
        int k = f >> 7;
        float h = fmaf(sD0[r], sF0[k],
                  fmaf(sD1[r], sF1[k],
                  fmaf(sD2[r], sF2[k], sFb[k])));
        As[0][r][k] = __float2bfloat16(fmaxf(h, 0.0f));
    }

    wmma::fragment<wmma::accumulator, 16,16,16, float> acc[4][4];
    #pragma unroll
    for (int i=0;i<4;i++)
        #pragma unroll
        for (int j=0;j<4;j++) wmma::fill_fragment(acc[i][j], 0.0f);

    const int nk = 8;
    for (int t = 0; t < nk; t++) {
        if (t + 1 < nk) { CP_WAIT1(); } else { CP_WAIT0(); }
        __syncthreads();
        int ab = t & 1, bb = t % 3;
        #pragma unroll
        for (int kk = 0; kk < 32; kk += 16) {
            wmma::fragment<wmma::matrix_a, 16,16,16, bf16, wmma::row_major> af[4];
            wmma::fragment<wmma::matrix_b, 16,16,16, bf16, wmma::row_major> bfr[4];
            #pragma unroll
            for (int i=0;i<4;i++) wmma::load_matrix_sync(af[i], &As[ab][wr+i*16][kk], 40);
            #pragma unroll
            for (int j=0;j<4;j++)
                wmma::load_matrix_sync(bfr[j], Bs + bb*32*SB + kk*SB + wc + j*16, SB);
            #pragma unroll
            for (int i=0;i<4;i++)
                #pragma unroll
                for (int j=0;j<4;j++)
                    wmma::mma_sync(acc[i][j], af[i], bfr[j], acc[i][j]);
        }
        if (t + 2 < nk) {
            int nb = (t+2) % 3, k0 = (t+2) << 5;
            #pragma unroll
            for (int i=0;i<4;i++){
                int f = tid + i*256, r = f >> 5, c = (f & 31) * 8;
                cpa16(saddr(Bs + nb*32*SB + r*SB + c), g_w_fd2 + (size_t)(k0+r)*DM_ + c);
            }
            CP_COMMIT();
        }
        if (t + 1 < nk) {
            int nb = (t+1) & 1, k0 = (t+1) << 5;
            #pragma unroll
            for (int e = 0; e < 16; e++) {
                int f = tid + e * 256;
                int r = f & 127;
                int k = f >> 7;
                int tc = k0 + k;
                float h = fmaf(sD0[r], sF0[tc],
                          fmaf(sD1[r], sF1[tc],
                          fmaf(sD2[r], sF2[tc], sFb[tc])));
                As[nb][r][k] = __float2bfloat16(fmaxf(h, 0.0f));
            }
        }
    }

    #pragma unroll
    for (int i=0;i<4;i++)
        #pragma unroll
        for (int j=0;j<4;j++) {
            wmma::store_matrix_sync(&Cs[wid][0][0], acc[i][j], 20, wmma::mem_row_major);
            __syncwarp();
            int rloc  = wr + i*16;
            int cbase = wc + j*16;
            #pragma unroll
            for (int e=0;e<4;e++){
                int p  = lane*4 + e;
                int rr = p >> 3;
                int cc = (p & 7) * 2;
                int rl = rloc + rr;
                int r  = row0 + rl;
                float pos0 = Cs[wid][rr][cc]   + fd2b[cbase+cc];
                float pos1 = Cs[wid][rr][cc+1] + fd2b[cbase+cc+1];
                size_t qoff = (size_t)sQ[rl] * DM_ + cbase + cc;
                size_t soff = (size_t)sS[rl] * DM_ + cbase + cc;
                float2 qv = __bfloat1622float2(*reinterpret_cast<const bf162*>(g_qb + qoff));
                float2 kv = __bfloat1622float2(*reinterpret_cast<const bf162*>(g_kb + soff));
                float2 vv = __bfloat1622float2(*reinterpret_cast<const bf162*>(g_vb + soff));
                size_t off = (size_t)r * DM_ + cbase + cc;
                *reinterpret_cast<bf162*>(g_gb + off) =
                    __float22bfloat162_rn(make_float2(qv.x - kv.x + pos0, qv.y - kv.y + pos1));
                *reinterpret_cast<bf162*>(g_vpb + off) =
                    __float22bfloat162_rn(make_float2(vv.x + pos0, vv.y + pos1));
            }
            __syncwarp();
        }
}

// --------------------------------- launch ------------------------------------
extern "C" void kernel_launch(void* const* d_in, const int* in_sizes, int n_in,
                              void* d_out, int out_size)
{
    const float* xyz   = (const float*)d_in[0];
    const float* feat  = (const float*)d_in[1];
    const float* xyzs  = (const float*)d_in[2];
    const float* feats = (const float*)d_in[3];
    const float* fc1w  = (const float*)d_in[4];
    const float* fc1b  = (const float*)d_in[5];
    const float* fc1sw = (const float*)d_in[6];
    const float* fc1sb = (const float*)d_in[7];
    const float* fc2w  = (const float*)d_in[8];
    const float* fc2b  = (const float*)d_in[9];
    const float* fd1w  = (const float*)d_in[10];
    const float* fd1b  = (const float*)d_in[11];
    const float* fd2w  = (const float*)d_in[12];
    const float* fd2b  = (const float*)d_in[13];
    const float* fg1w  = (const float*)d_in[14];
    const float* fg1b  = (const float*)d_in[15];
    const float* fg2w  = (const float*)d_in[16];
    const float* fg2b  = (const float*)d_in[17];
    const float* wk    = (const float*)d_in[18];
    const float* wv    = (const float*)d_in[19];

    static bool init = false;
    static bf16 *p_featb, *p_featsb, *p_qb, *p_xsb, *p_kb, *p_vb, *p_gb, *p_hb, *p_resb;
    static bf16 *pw_fc1, *pw_fc1s, *pw_wk, *pw_wv, *pw_fd2, *pw_fg1, *pw_fg2, *pw_fc2;
    static float *p_outtmp, *p_zero;
    if (!init) {
        cudaGetSymbolAddress((void**)&p_featb,  g_featb);
        cudaGetSymbolAddress((void**)&p_featsb, g_featsb);
        cudaGetSymbolAddress((void**)&p_qb,  g_qb);
        cudaGetSymbolAddress((void**)&p_xsb, g_xsb);
        cudaGetSymbolAddress((void**)&p_kb,  g_kb);
        cudaGetSymbolAddress((void**)&p_vb,  g_vb);
        cudaGetSymbolAddress((void**)&p_gb,  g_gb);
        cudaGetSymbolAddress((void**)&p_hb,  g_hb);
        cudaGetSymbolAddress((void**)&p_resb, g_resb);
        cudaGetSymbolAddress((void**)&pw_fc1,  g_w_fc1);
        cudaGetSymbolAddress((void**)&pw_fc1s, g_w_fc1s);
        cudaGetSymbolAddress((void**)&pw_wk,   g_w_wk);
        cudaGetSymbolAddress((void**)&pw_wv,   g_w_wv);
        cudaGetSymbolAddress((void**)&pw_fd2,  g_w_fd2);
        cudaGetSymbolAddress((void**)&pw_fg1,  g_w_fg1);
        cudaGetSymbolAddress((void**)&pw_fg2,  g_w_fg2);
        cudaGetSymbolAddress((void**)&pw_fc2,  g_w_fc2);
        cudaGetSymbolAddress((void**)&p_outtmp, g_outtmp);
        cudaGetSymbolAddress((void**)&p_zero,   g_zerobias);

        cudaFuncSetAttribute(hgemm_k<128,256,false,false,true>,
                             cudaFuncAttributeMaxDynamicSharedMemorySize, HG_SMEM(256));
        cudaFuncSetAttribute(hgemm_k<256,256,false,false,true>,
                             cudaFuncAttributeMaxDynamicSharedMemorySize, HG_SMEM(256));
        cudaFuncSetAttribute(hgemm_k<256,256,true,false,true>,
                             cudaFuncAttributeMaxDynamicSharedMemorySize, HG_SMEM(256));
        cudaFuncSetAttribute(hgemm_k<256,128,false,true,false>,
                             cudaFuncAttributeMaxDynamicSharedMemorySize, HG_SMEM(128));
        cudaFuncSetAttribute(attn_k,
                             cudaFuncAttributeMaxDynamicSharedMemorySize, AT_SMEM);
        cudaFuncSetAttribute(posg_k,
                             cudaFuncAttributeMaxDynamicSharedMemorySize, PG_SMEM);
        init = true;
    }

    const long long OUTE  = (long long)BN_ * DP_;     //  2,097,152
    const long long ATTNE = (long long)BNK_ * DM_;    // 67,108,864
    float* out = (float*)d_out;
    float* out_main; float* out_attn; int write_attn;
    if ((long long)out_size >= OUTE + ATTNE) { out_main = out; out_attn = out + OUTE; write_attn = 1; }
    else if ((long long)out_size == ATTNE)   { out_main = p_outtmp; out_attn = out; write_attn = 1; }
    else                                      { out_main = out; out_attn = nullptr; write_attn = 0; }

    // 1. KNN (exact fp32)
    knn_k<<<dim3(B_, N_/128), 128>>>(xyz, xyzs);

    // 2. all fp32->bf16 conversions in ONE launch
    CvtArgs ca;
    ca.s[0]=feat;  ca.d[0]=p_featb;
    ca.s[1]=feats; ca.d[1]=p_featsb;
    ca.s[2]=fc1w;  ca.d[2]=pw_fc1;
    ca.s[3]=fc1sw; ca.d[3]=pw_fc1s;
    ca.s[4]=wk;    ca.d[4]=pw_wk;
    ca.s[5]=wv;    ca.d[5]=pw_wv;
    ca.s[6]=fd2w;  ca.d[6]=pw_fd2;
    ca.s[7]=fg1w;  ca.d[7]=pw_fg1;
    ca.s[8]=fg2w;  ca.d[8]=pw_fg2;
    ca.s[9]=fc2w;  ca.d[9]=pw_fc2;
    cvtall_k<<<CVT_BLOCKS, 256>>>(ca);

    // 3. q = feat @ fc1 + b ; xs = feats @ fc1s + b   (full 256-wide tiles)
    hgemm_k<128,256,false,false,true><<<BN_/128, 256, HG_SMEM(256)>>>(p_featb,  pw_fc1,  DM_, fc1b,  nullptr, p_qb);
    hgemm_k<128,256,false,false,true><<<BN_/128, 256, HG_SMEM(256)>>>(p_featsb, pw_fc1s, DM_, fc1sb, nullptr, p_xsb);
    // 4. k_all = xs @ wk ; v_all = xs @ wv
    hgemm_k<256,256,false,false,true><<<BN_/128, 256, HG_SMEM(256)>>>(p_xsb, pw_wk, DM_, p_zero, nullptr, p_kb);
    hgemm_k<256,256,false,false,true><<<BN_/128, 256, HG_SMEM(256)>>>(p_xsb, pw_wv, DM_, p_zero, nullptr, p_vb);
    // 5. fused pos GEMM -> g (bf16), vp (bf16)
    posg_k<<<BNK_/128, 256, PG_SMEM>>>(xyz, xyzs, fd1w, fd1b, fd2b);
    // 6. h = relu(g @ fg1 + b)
    hgemm_k<256,256,true,false,true><<<BNK_/128, 256, HG_SMEM(256)>>>(p_gb, pw_fg1, DM_, fg1b, nullptr, p_hb);
    // 7+8. a = h @ fg2 + b -> softmax(K) -> res  (fused, no g_gb round-trip)
    attn_k<<<BNK_/128, 256, AT_SMEM>>>(p_hb, pw_fg2, fg2b, out_attn, write_attn);
    // 9. out = features + res @ fc2 + b   (fp32 output, fp32 residual add)
    hgemm_k<256,128,false,true,false><<<BN_/128, 256, HG_SMEM(128)>>>(p_resb, pw_fc2, DP_, fc2b, feat, out_main);
}